// round 7
// baseline (speedup 1.0000x reference)
#include <cuda_runtime.h>
#include <cuda_bf16.h>
#include <cstdint>

#define N1 262144
#define N2 65536
#define KNN 16
#define MPAIR (N2*KNN)
#define EPSV 1e-5f

// ---- static scratch (no runtime allocation allowed) ----
__device__ float  g_upfeat[N2*64];   // relu(bn(x2@w2^T))
__device__ float  g_pre[N2*64];      // x2-part of shrinker linear
__device__ float  g_acc[N1*64];      // softmax-weighted numerator
__device__ float  g_denom[N1];       // softmax denominator
__device__ float4 g_p1q[N1];         // packed p1 (xyz_)
__device__ float4 g_p2q[N2];         // packed p2 (xyz_)

// ================= init: zero acc/denom + pack p1/p2 into float4 =================
__global__ void __launch_bounds__(256)
init_kernel(const float* __restrict__ p1, const float* __restrict__ p2) {
    int gid = blockIdx.x * 256 + threadIdx.x;      // [0, N1*16)
    ((float4*)g_acc)[gid] = make_float4(0.f, 0.f, 0.f, 0.f);
    if (gid < N1) {
        g_denom[gid] = 0.0f;
        g_p1q[gid] = make_float4(p1[3*gid], p1[3*gid+1], p1[3*gid+2], 0.f);
    }
    if (gid < N2)
        g_p2q[gid] = make_float4(p2[3*gid], p2[3*gid+1], p2[3*gid+2], 0.f);
}

// bf16 mma (baseline ISA, sm_80+; lowers to HMMA on sm_103 tensor pipe)
__device__ __forceinline__ void mma16816(float* d, const uint32_t* a, uint32_t b0, uint32_t b1) {
    asm volatile(
        "mma.sync.aligned.m16n8k16.row.col.f32.bf16.bf16.f32 "
        "{%0,%1,%2,%3}, {%4,%5,%6,%7}, {%8,%9}, {%0,%1,%2,%3};"
        : "+f"(d[0]), "+f"(d[1]), "+f"(d[2]), "+f"(d[3])
        : "r"(a[0]), "r"(a[1]), "r"(a[2]), "r"(a[3]), "r"(b0), "r"(b1));
}

__device__ __forceinline__ void split2(float f0, float f1, uint32_t& hi, uint32_t& lo) {
    __nv_bfloat16 h0 = __float2bfloat16_rn(f0);
    __nv_bfloat16 h1 = __float2bfloat16_rn(f1);
    __nv_bfloat162 hp; hp.x = h0; hp.y = h1;
    __nv_bfloat162 lp = __floats2bfloat162_rn(f0 - __bfloat162float(h0),
                                              f1 - __bfloat162float(h1));
    hi = *(uint32_t*)&hp;
    lo = *(uint32_t*)&lp;
}

// Pack BN-folded W into smem as bf16 hi/lo k-pairs in the k-permuted layout.
__device__ __forceinline__ void fill_packB(uint32_t* packB, float* fb,
                                           const float* __restrict__ w, int wstride, int wcol0,
                                           const float* __restrict__ bb,
                                           const float* __restrict__ gg,
                                           const float* __restrict__ be,
                                           const float* __restrict__ mm,
                                           const float* __restrict__ vv,
                                           int tid)
{
    if (tid < 64) {
        float s = gg[tid] * rsqrtf(vv[tid] + EPSV);
        fb[tid] = (bb[tid] - mm[tid]) * s + be[tid];
    }
    #pragma unroll
    for (int it = 0; it < 16; it++) {
        int idx = it * 256 + tid;
        int row = idx >> 6, col = idx & 63;
        int r31 = row & 31;
        int ks = r31 >> 3, q = r31 & 7;
        int kk = 16 * ks + ((q < 4) ? 4 * q : 4 * (q - 4) + 2);
        float s  = gg[col] * rsqrtf(vv[col] + EPSV);
        float w0 = w[col * wstride + wcol0 + kk]     * s;
        float w1 = w[col * wstride + wcol0 + kk + 1] * s;
        uint32_t hiw, low;
        split2(w0, w1, hiw, low);
        packB[row * 64 + (col ^ ((row & 3) << 3))] = (row < 32) ? hiw : low;
    }
}

__device__ __forceinline__ void load_A(const float* __restrict__ x, int m0, int gq, int tq,
                                       uint32_t Ah[4][4], uint32_t Al[4][4])
{
    const float4* r0 = (const float4*)(x + (size_t)(m0 + gq) * 64);
    const float4* r1 = (const float4*)(x + (size_t)(m0 + gq + 8) * 64);
    #pragma unroll
    for (int ks = 0; ks < 4; ks++) {
        float4 v0 = r0[4 * ks + tq];
        float4 v1 = r1[4 * ks + tq];
        split2(v0.x, v0.y, Ah[ks][0], Al[ks][0]);
        split2(v1.x, v1.y, Ah[ks][1], Al[ks][1]);
        split2(v0.z, v0.w, Ah[ks][2], Al[ks][2]);
        split2(v1.z, v1.w, Ah[ks][3], Al[ks][3]);
    }
}

// 3 accumulating chains over HALF the n-tiles (nt0..nt0+3): acc is 16 regs.
__device__ __forceinline__ void run_chains_half(float acc[4][4], const uint32_t* packB,
                                                const uint32_t Ah[4][4], const uint32_t Al[4][4],
                                                int gq, int tq, int nt0)
{
    const int csw = tq << 3;
    #pragma unroll
    for (int c = 0; c < 3; c++) {
        const uint32_t (*Af)[4] = (c == 2) ? Al : Ah;
        const int rb = (c == 1) ? 32 : 0;
        #pragma unroll
        for (int ks = 0; ks < 4; ks++) {
            const int r0i = (rb + 8 * ks + tq) * 64;
            const int r1i = (rb + 8 * ks + tq + 4) * 64;
            #pragma unroll
            for (int nt = 0; nt < 4; nt++) {
                int coff = (8 * (nt0 + nt) + gq) ^ csw;
                mma16816(acc[nt], Af[ks], packB[r0i + coff], packB[r1i + coff]);
            }
        }
    }
}

__device__ __forceinline__ void epilogue_half(float acc[4][4], const float* fb,
                                              float* __restrict__ o, int m0, int gq, int tq,
                                              int nt0, bool relu)
{
    float* o0 = o + (size_t)(m0 + gq) * 64;
    float* o1 = o + (size_t)(m0 + gq + 8) * 64;
    #pragma unroll
    for (int nt = 0; nt < 4; nt++) {
        int col = 8 * (nt0 + nt) + 2 * tq;
        float2 fbp = *(float2*)&fb[col];
        float2 u, v;
        u.x = acc[nt][0] + fbp.x; u.y = acc[nt][1] + fbp.y;
        v.x = acc[nt][2] + fbp.x; v.y = acc[nt][3] + fbp.y;
        if (relu) {
            u.x = fmaxf(u.x, 0.f); u.y = fmaxf(u.y, 0.f);
            v.x = fmaxf(v.x, 0.f); v.y = fmaxf(v.y, 0.f);
        }
        *(float2*)(o0 + col) = u;
        *(float2*)(o1 + col) = v;
    }
}

// ============ N1 GEMM (runs LAST): out = relu(bn(x1@w1^T)) + acc/denom ============
__global__ void __launch_bounds__(256, 3)
gemm_n1_kernel(const float* __restrict__ x,
               const float* __restrict__ w,
               const float* __restrict__ bb, const float* __restrict__ gg,
               const float* __restrict__ be, const float* __restrict__ mm,
               const float* __restrict__ vv,
               float* __restrict__ outp)
{
    __shared__ uint32_t packB[64 * 64];
    __shared__ float fb[64];
    const int tid = threadIdx.x, wid = tid >> 5, lane = tid & 31;
    const int gq = lane >> 2, tq = lane & 3;

    fill_packB(packB, fb, w, 64, 0, bb, gg, be, mm, vv, tid);
    __syncthreads();

    for (int t = blockIdx.x; t < N1 / 128; t += gridDim.x) {
        const int m0 = t * 128 + wid * 16;
        uint32_t Ah[4][4], Al[4][4];
        load_A(x, m0, gq, tq, Ah, Al);

        const int row0 = m0 + gq, row1 = m0 + gq + 8;
        float dn0 = g_denom[row0], dn1 = g_denom[row1];
        float rc0 = dn0 > 0.f ? 1.0f / dn0 : 0.0f;
        float rc1 = dn1 > 0.f ? 1.0f / dn1 : 0.0f;
        const float* a0 = g_acc + (size_t)row0 * 64;
        const float* a1 = g_acc + (size_t)row1 * 64;
        float* o0 = outp + (size_t)row0 * 64;
        float* o1 = outp + (size_t)row1 * 64;

        #pragma unroll
        for (int half = 0; half < 2; half++) {
            float acc[4][4];
            #pragma unroll
            for (int nt = 0; nt < 4; nt++)
                #pragma unroll
                for (int r = 0; r < 4; r++) acc[nt][r] = 0.0f;
            run_chains_half(acc, packB, Ah, Al, gq, tq, half * 4);
            #pragma unroll
            for (int nt = 0; nt < 4; nt++) {
                int col = 8 * (half * 4 + nt) + 2 * tq;
                float2 fbp = *(float2*)&fb[col];
                float2 s0 = *(const float2*)(a0 + col);
                float2 s1 = *(const float2*)(a1 + col);
                float2 u, v;
                u.x = fmaxf(acc[nt][0] + fbp.x, 0.f) + s0.x * rc0;
                u.y = fmaxf(acc[nt][1] + fbp.y, 0.f) + s0.y * rc0;
                v.x = fmaxf(acc[nt][2] + fbp.x, 0.f) + s1.x * rc1;
                v.y = fmaxf(acc[nt][3] + fbp.y, 0.f) + s1.y * rc1;
                *(float2*)(o0 + col) = u;
                *(float2*)(o1 + col) = v;
            }
        }
    }
}

// ============ N2 fused GEMM: upfeat (w2, relu) + pre (ws1[:,3:], no relu) ============
__global__ void __launch_bounds__(256, 3)
gemm_n2_kernel(const float* __restrict__ x,
               const float* __restrict__ w2,
               const float* __restrict__ b2, const float* __restrict__ g2,
               const float* __restrict__ be2, const float* __restrict__ m2,
               const float* __restrict__ v2,
               const float* __restrict__ ws1,
               const float* __restrict__ bs1, const float* __restrict__ gs,
               const float* __restrict__ bes, const float* __restrict__ ms,
               const float* __restrict__ vs)
{
    __shared__ uint32_t packB2[64 * 64];
    __shared__ uint32_t packBs[64 * 64];
    __shared__ float fb2[64], fbs[64];
    const int tid = threadIdx.x, wid = tid >> 5, lane = tid & 31;
    const int gq = lane >> 2, tq = lane & 3;

    fill_packB(packB2, fb2, w2, 64, 0, b2, g2, be2, m2, v2, tid);
    fill_packB(packBs, fbs, ws1, 67, 3, bs1, gs, bes, ms, vs, tid);
    __syncthreads();

    for (int t = blockIdx.x; t < N2 / 128; t += gridDim.x) {
        const int m0 = t * 128 + wid * 16;
        uint32_t Ah[4][4], Al[4][4];
        load_A(x, m0, gq, tq, Ah, Al);

        #pragma unroll
        for (int half = 0; half < 2; half++) {
            float acc[4][4];
            #pragma unroll
            for (int nt = 0; nt < 4; nt++)
                #pragma unroll
                for (int r = 0; r < 4; r++) acc[nt][r] = 0.0f;
            run_chains_half(acc, packB2, Ah, Al, gq, tq, half * 4);
            epilogue_half(acc, fb2, g_upfeat, m0, gq, tq, half * 4, true);

            #pragma unroll
            for (int nt = 0; nt < 4; nt++)
                #pragma unroll
                for (int r = 0; r < 4; r++) acc[nt][r] = 0.0f;
            run_chains_half(acc, packBs, Ah, Al, gq, tq, half * 4);
            epilogue_half(acc, fbs, g_pre, m0, gq, tq, half * 4, false);
        }
    }
}

// ========== fused pair pass v2: warp-local, 8 threads per pair ==========
// Thread (pair mi, channel group cg = tid&7) owns channels [8cg, 8cg+8):
// shrinker weights in REGISTERS (loaded once; persistent grid-stride loop).
// logit partial -> 3x shfl.bfly reduce -> exp -> denom atomic (1 lane)
// -> weighted numerator scatter with 2 float4 RED.128 per thread.
// No shared memory, no __syncthreads.
__global__ void __launch_bounds__(256)
pair_kernel(const int*   __restrict__ knn,
            const float* __restrict__ ws1,
            const float* __restrict__ gsv,
            const float* __restrict__ vsv,
            const float* __restrict__ ws2,
            const float* __restrict__ bs2)
{
    const int tid = threadIdx.x;
    const int cg  = tid & 7;          // channel group
    const int pp  = tid >> 3;         // pair slot within block (0..31)

    // per-thread weights for channels c = 8*cg + q
    float w3x[8], w3y[8], w3z[8], w2r[8];
    #pragma unroll
    for (int q = 0; q < 8; q++) {
        int c = 8 * cg + q;
        float s = gsv[c] * rsqrtf(vsv[c] + EPSV);
        w3x[q] = ws1[c * 67 + 0] * s;
        w3y[q] = ws1[c * 67 + 1] * s;
        w3z[q] = ws1[c * 67 + 2] * s;
        w2r[q] = ws2[c];
    }
    const float bias2 = bs2[0];

    for (int mi = blockIdx.x * 32 + pp; mi < MPAIR; mi += gridDim.x * 32) {
        const int j = mi >> 4;
        const int i = knn[mi];
        float4 pq = g_p1q[i];          // 8 lanes same addr -> 1 line
        float4 qq = g_p2q[j];
        float prx = pq.x - qq.x, pry = pq.y - qq.y, prz = pq.z - qq.z;

        // 8 channels of the shrinker MLP
        const float4* pre4 = (const float4*)(g_pre + (size_t)j * 64) + 2 * cg;
        float4 pv0 = pre4[0];
        float4 pv1 = pre4[1];
        float part = 0.0f, h;
        h = fmaf(prx, w3x[0], fmaf(pry, w3y[0], fmaf(prz, w3z[0], pv0.x)));
        part = fmaf(fmaxf(h, 0.f), w2r[0], part);
        h = fmaf(prx, w3x[1], fmaf(pry, w3y[1], fmaf(prz, w3z[1], pv0.y)));
        part = fmaf(fmaxf(h, 0.f), w2r[1], part);
        h = fmaf(prx, w3x[2], fmaf(pry, w3y[2], fmaf(prz, w3z[2], pv0.z)));
        part = fmaf(fmaxf(h, 0.f), w2r[2], part);
        h = fmaf(prx, w3x[3], fmaf(pry, w3y[3], fmaf(prz, w3z[3], pv0.w)));
        part = fmaf(fmaxf(h, 0.f), w2r[3], part);
        h = fmaf(prx, w3x[4], fmaf(pry, w3y[4], fmaf(prz, w3z[4], pv1.x)));
        part = fmaf(fmaxf(h, 0.f), w2r[4], part);
        h = fmaf(prx, w3x[5], fmaf(pry, w3y[5], fmaf(prz, w3z[5], pv1.y)));
        part = fmaf(fmaxf(h, 0.f), w2r[5], part);
        h = fmaf(prx, w3x[6], fmaf(pry, w3y[6], fmaf(prz, w3z[6], pv1.z)));
        part = fmaf(fmaxf(h, 0.f), w2r[6], part);
        h = fmaf(prx, w3x[7], fmaf(pry, w3y[7], fmaf(prz, w3z[7], pv1.w)));
        part = fmaf(fmaxf(h, 0.f), w2r[7], part);

        // reduce across the 8 lanes of this pair
        part += __shfl_xor_sync(0xffffffffu, part, 1);
        part += __shfl_xor_sync(0xffffffffu, part, 2);
        part += __shfl_xor_sync(0xffffffffu, part, 4);

        float ev = __expf(part + bias2);
        if (cg == 0) atomicAdd(&g_denom[i], ev);

        // weighted numerator scatter: this thread's 8 channels
        const float4* uf4 = (const float4*)(g_upfeat + (size_t)j * 64) + 2 * cg;
        float4 u0 = uf4[0], u1 = uf4[1];
        float4* dst = (float4*)(g_acc + (size_t)i * 64) + 2 * cg;
        atomicAdd(dst,     make_float4(u0.x * ev, u0.y * ev, u0.z * ev, u0.w * ev));
        atomicAdd(dst + 1, make_float4(u1.x * ev, u1.y * ev, u1.z * ev, u1.w * ev));
    }
}

extern "C" void kernel_launch(void* const* d_in, const int* in_sizes, int n_in,
                              void* d_out, int out_size)
{
    const float* p1  = (const float*)d_in[0];
    const float* p2  = (const float*)d_in[1];
    const float* x1  = (const float*)d_in[2];
    const float* x2  = (const float*)d_in[3];
    const int*   knn = (const int*)  d_in[4];
    const float* w1  = (const float*)d_in[5];
    const float* b1  = (const float*)d_in[6];
    const float* g1  = (const float*)d_in[7];
    const float* be1 = (const float*)d_in[8];
    const float* m1  = (const float*)d_in[9];
    const float* v1  = (const float*)d_in[10];
    const float* w2  = (const float*)d_in[11];
    const float* b2  = (const float*)d_in[12];
    const float* g2  = (const float*)d_in[13];
    const float* be2 = (const float*)d_in[14];
    const float* m2  = (const float*)d_in[15];
    const float* v2  = (const float*)d_in[16];
    const float* ws1 = (const float*)d_in[17];
    const float* bs1 = (const float*)d_in[18];
    const float* gs  = (const float*)d_in[19];
    const float* bes = (const float*)d_in[20];
    const float* ms  = (const float*)d_in[21];
    const float* vs  = (const float*)d_in[22];
    const float* ws2 = (const float*)d_in[23];
    const float* bs2 = (const float*)d_in[24];
    float* out = (float*)d_out;

    // zero acc/denom + pack p1/p2
    init_kernel<<<N1*16/256, 256>>>(p1, p2);
    // upfeat + pre (share x2 reads and A conversion)
    gemm_n2_kernel<<<444, 256>>>(x2, w2, b2, g2, be2, m2, v2,
                                 ws1, bs1, gs, bes, ms, vs);
    // fused logit + exp + denom + weighted numerator scatter (warp-local)
    pair_kernel<<<1184, 256>>>(knn, ws1, gs, vs, ws2, bs2);
    // y1 GEMM + final normalize: out = relu(bn(x1@w1)) + acc/denom
    gemm_n1_kernel<<<444, 256>>>(x1, w1, b1, g1, be1, m1, v1, out);
}

// round 8
// speedup vs baseline: 1.1437x; 1.1437x over previous
#include <cuda_runtime.h>
#include <cuda_bf16.h>
#include <cstdint>

#define N1 262144
#define N2 65536
#define KNN 16
#define MPAIR (N2*KNN)
#define EPSV 1e-5f

// ---- static scratch (no runtime allocation allowed) ----
__device__ float  g_upfeat[N2*64];   // relu(bn(x2@w2^T))
__device__ float  g_pre[N2*64];      // x2-part of shrinker linear
__device__ float  g_acc[N1*64];      // softmax-weighted numerator
__device__ float  g_denom[N1];       // softmax denominator
__device__ float4 g_p1q[N1];         // packed p1 (xyz_)
__device__ float4 g_p2q[N2];         // packed p2 (xyz_)

// ================= init: zero acc/denom + pack p1/p2 into float4 =================
__global__ void __launch_bounds__(256)
init_kernel(const float* __restrict__ p1, const float* __restrict__ p2) {
    int gid = blockIdx.x * 256 + threadIdx.x;      // [0, N1*16)
    ((float4*)g_acc)[gid] = make_float4(0.f, 0.f, 0.f, 0.f);
    if (gid < N1) {
        g_denom[gid] = 0.0f;
        g_p1q[gid] = make_float4(p1[3*gid], p1[3*gid+1], p1[3*gid+2], 0.f);
    }
    if (gid < N2)
        g_p2q[gid] = make_float4(p2[3*gid], p2[3*gid+1], p2[3*gid+2], 0.f);
}

// bf16 mma (baseline ISA, sm_80+; lowers to HMMA on sm_103 tensor pipe)
__device__ __forceinline__ void mma16816(float* d, const uint32_t* a, uint32_t b0, uint32_t b1) {
    asm volatile(
        "mma.sync.aligned.m16n8k16.row.col.f32.bf16.bf16.f32 "
        "{%0,%1,%2,%3}, {%4,%5,%6,%7}, {%8,%9}, {%0,%1,%2,%3};"
        : "+f"(d[0]), "+f"(d[1]), "+f"(d[2]), "+f"(d[3])
        : "r"(a[0]), "r"(a[1]), "r"(a[2]), "r"(a[3]), "r"(b0), "r"(b1));
}

__device__ __forceinline__ void split2(float f0, float f1, uint32_t& hi, uint32_t& lo) {
    __nv_bfloat16 h0 = __float2bfloat16_rn(f0);
    __nv_bfloat16 h1 = __float2bfloat16_rn(f1);
    __nv_bfloat162 hp; hp.x = h0; hp.y = h1;
    __nv_bfloat162 lp = __floats2bfloat162_rn(f0 - __bfloat162float(h0),
                                              f1 - __bfloat162float(h1));
    hi = *(uint32_t*)&hp;
    lo = *(uint32_t*)&lp;
}

// Pack BN-folded W into smem as bf16 hi/lo k-pairs in the k-permuted layout.
__device__ __forceinline__ void fill_packB(uint32_t* packB, float* fb,
                                           const float* __restrict__ w, int wstride, int wcol0,
                                           const float* __restrict__ bb,
                                           const float* __restrict__ gg,
                                           const float* __restrict__ be,
                                           const float* __restrict__ mm,
                                           const float* __restrict__ vv,
                                           int tid)
{
    if (tid < 64) {
        float s = gg[tid] * rsqrtf(vv[tid] + EPSV);
        fb[tid] = (bb[tid] - mm[tid]) * s + be[tid];
    }
    #pragma unroll
    for (int it = 0; it < 16; it++) {
        int idx = it * 256 + tid;
        int row = idx >> 6, col = idx & 63;
        int r31 = row & 31;
        int ks = r31 >> 3, q = r31 & 7;
        int kk = 16 * ks + ((q < 4) ? 4 * q : 4 * (q - 4) + 2);
        float s  = gg[col] * rsqrtf(vv[col] + EPSV);
        float w0 = w[col * wstride + wcol0 + kk]     * s;
        float w1 = w[col * wstride + wcol0 + kk + 1] * s;
        uint32_t hiw, low;
        split2(w0, w1, hiw, low);
        packB[row * 64 + (col ^ ((row & 3) << 3))] = (row < 32) ? hiw : low;
    }
}

__device__ __forceinline__ void load_A(const float* __restrict__ x, int m0, int gq, int tq,
                                       uint32_t Ah[4][4], uint32_t Al[4][4])
{
    const float4* r0 = (const float4*)(x + (size_t)(m0 + gq) * 64);
    const float4* r1 = (const float4*)(x + (size_t)(m0 + gq + 8) * 64);
    #pragma unroll
    for (int ks = 0; ks < 4; ks++) {
        float4 v0 = r0[4 * ks + tq];
        float4 v1 = r1[4 * ks + tq];
        split2(v0.x, v0.y, Ah[ks][0], Al[ks][0]);
        split2(v1.x, v1.y, Ah[ks][1], Al[ks][1]);
        split2(v0.z, v0.w, Ah[ks][2], Al[ks][2]);
        split2(v1.z, v1.w, Ah[ks][3], Al[ks][3]);
    }
}

// 3 accumulating chains over HALF the n-tiles (nt0..nt0+3): acc is 16 regs.
__device__ __forceinline__ void run_chains_half(float acc[4][4], const uint32_t* packB,
                                                const uint32_t Ah[4][4], const uint32_t Al[4][4],
                                                int gq, int tq, int nt0)
{
    const int csw = tq << 3;
    #pragma unroll
    for (int c = 0; c < 3; c++) {
        const uint32_t (*Af)[4] = (c == 2) ? Al : Ah;
        const int rb = (c == 1) ? 32 : 0;
        #pragma unroll
        for (int ks = 0; ks < 4; ks++) {
            const int r0i = (rb + 8 * ks + tq) * 64;
            const int r1i = (rb + 8 * ks + tq + 4) * 64;
            #pragma unroll
            for (int nt = 0; nt < 4; nt++) {
                int coff = (8 * (nt0 + nt) + gq) ^ csw;
                mma16816(acc[nt], Af[ks], packB[r0i + coff], packB[r1i + coff]);
            }
        }
    }
}

__device__ __forceinline__ void epilogue_half(float acc[4][4], const float* fb,
                                              float* __restrict__ o, int m0, int gq, int tq,
                                              int nt0, bool relu)
{
    float* o0 = o + (size_t)(m0 + gq) * 64;
    float* o1 = o + (size_t)(m0 + gq + 8) * 64;
    #pragma unroll
    for (int nt = 0; nt < 4; nt++) {
        int col = 8 * (nt0 + nt) + 2 * tq;
        float2 fbp = *(float2*)&fb[col];
        float2 u, v;
        u.x = acc[nt][0] + fbp.x; u.y = acc[nt][1] + fbp.y;
        v.x = acc[nt][2] + fbp.x; v.y = acc[nt][3] + fbp.y;
        if (relu) {
            u.x = fmaxf(u.x, 0.f); u.y = fmaxf(u.y, 0.f);
            v.x = fmaxf(v.x, 0.f); v.y = fmaxf(v.y, 0.f);
        }
        *(float2*)(o0 + col) = u;
        *(float2*)(o1 + col) = v;
    }
}

// ============ N1 GEMM (runs LAST): out = relu(bn(x1@w1^T)) + acc/denom ============
__global__ void __launch_bounds__(256, 3)
gemm_n1_kernel(const float* __restrict__ x,
               const float* __restrict__ w,
               const float* __restrict__ bb, const float* __restrict__ gg,
               const float* __restrict__ be, const float* __restrict__ mm,
               const float* __restrict__ vv,
               float* __restrict__ outp)
{
    __shared__ uint32_t packB[64 * 64];
    __shared__ float fb[64];
    const int tid = threadIdx.x, wid = tid >> 5, lane = tid & 31;
    const int gq = lane >> 2, tq = lane & 3;

    fill_packB(packB, fb, w, 64, 0, bb, gg, be, mm, vv, tid);
    __syncthreads();

    for (int t = blockIdx.x; t < N1 / 128; t += gridDim.x) {
        const int m0 = t * 128 + wid * 16;
        uint32_t Ah[4][4], Al[4][4];
        load_A(x, m0, gq, tq, Ah, Al);

        const int row0 = m0 + gq, row1 = m0 + gq + 8;
        float dn0 = g_denom[row0], dn1 = g_denom[row1];
        float rc0 = dn0 > 0.f ? 1.0f / dn0 : 0.0f;
        float rc1 = dn1 > 0.f ? 1.0f / dn1 : 0.0f;
        const float* a0 = g_acc + (size_t)row0 * 64;
        const float* a1 = g_acc + (size_t)row1 * 64;
        float* o0 = outp + (size_t)row0 * 64;
        float* o1 = outp + (size_t)row1 * 64;

        #pragma unroll
        for (int half = 0; half < 2; half++) {
            float acc[4][4];
            #pragma unroll
            for (int nt = 0; nt < 4; nt++)
                #pragma unroll
                for (int r = 0; r < 4; r++) acc[nt][r] = 0.0f;
            run_chains_half(acc, packB, Ah, Al, gq, tq, half * 4);
            #pragma unroll
            for (int nt = 0; nt < 4; nt++) {
                int col = 8 * (half * 4 + nt) + 2 * tq;
                float2 fbp = *(float2*)&fb[col];
                float2 s0 = *(const float2*)(a0 + col);
                float2 s1 = *(const float2*)(a1 + col);
                float2 u, v;
                u.x = fmaxf(acc[nt][0] + fbp.x, 0.f) + s0.x * rc0;
                u.y = fmaxf(acc[nt][1] + fbp.y, 0.f) + s0.y * rc0;
                v.x = fmaxf(acc[nt][2] + fbp.x, 0.f) + s1.x * rc1;
                v.y = fmaxf(acc[nt][3] + fbp.y, 0.f) + s1.y * rc1;
                *(float2*)(o0 + col) = u;
                *(float2*)(o1 + col) = v;
            }
        }
    }
}

// ============ N2 fused GEMM: upfeat (w2, relu) + pre (ws1[:,3:], no relu) ============
__global__ void __launch_bounds__(256, 3)
gemm_n2_kernel(const float* __restrict__ x,
               const float* __restrict__ w2,
               const float* __restrict__ b2, const float* __restrict__ g2,
               const float* __restrict__ be2, const float* __restrict__ m2,
               const float* __restrict__ v2,
               const float* __restrict__ ws1,
               const float* __restrict__ bs1, const float* __restrict__ gs,
               const float* __restrict__ bes, const float* __restrict__ ms,
               const float* __restrict__ vs)
{
    __shared__ uint32_t packB2[64 * 64];
    __shared__ uint32_t packBs[64 * 64];
    __shared__ float fb2[64], fbs[64];
    const int tid = threadIdx.x, wid = tid >> 5, lane = tid & 31;
    const int gq = lane >> 2, tq = lane & 3;

    fill_packB(packB2, fb2, w2, 64, 0, b2, g2, be2, m2, v2, tid);
    fill_packB(packBs, fbs, ws1, 67, 3, bs1, gs, bes, ms, vs, tid);
    __syncthreads();

    for (int t = blockIdx.x; t < N2 / 128; t += gridDim.x) {
        const int m0 = t * 128 + wid * 16;
        uint32_t Ah[4][4], Al[4][4];
        load_A(x, m0, gq, tq, Ah, Al);

        #pragma unroll
        for (int half = 0; half < 2; half++) {
            float acc[4][4];
            #pragma unroll
            for (int nt = 0; nt < 4; nt++)
                #pragma unroll
                for (int r = 0; r < 4; r++) acc[nt][r] = 0.0f;
            run_chains_half(acc, packB2, Ah, Al, gq, tq, half * 4);
            epilogue_half(acc, fb2, g_upfeat, m0, gq, tq, half * 4, true);

            #pragma unroll
            for (int nt = 0; nt < 4; nt++)
                #pragma unroll
                for (int r = 0; r < 4; r++) acc[nt][r] = 0.0f;
            run_chains_half(acc, packBs, Ah, Al, gq, tq, half * 4);
            epilogue_half(acc, fbs, g_pre, m0, gq, tq, half * 4, false);
        }
    }
}

// ========== fused pair pass: two-phase (R6 structure), phase 1 lane-split ==========
// Phase 1: 16 lanes per pair; lane owns channels [4c4, 4c4+4), weights in
// REGISTERS (zero LDS), 1 pre-LDG.128 per lane, logit via 4x shfl.bfly.
// e/i staged in smem. Phase 2 (unchanged, proven): 16-lane groups scatter
// 64 channels per pair with float4 vector atomics (RED.128).
__global__ void __launch_bounds__(256)
pair_kernel(const int*   __restrict__ knn,
            const float* __restrict__ ws1,
            const float* __restrict__ gsv,
            const float* __restrict__ vsv,
            const float* __restrict__ ws2,
            const float* __restrict__ bs2)
{
    __shared__ float se[256];
    __shared__ int   si[256];
    const int tid  = threadIdx.x;
    const int lane = tid & 31, w = tid >> 5;
    const int sub  = lane >> 4;        // pair slot within warp iteration (0/1)
    const int c4   = lane & 15;        // float4 channel group within pair

    // per-lane weights for channels c = 4*c4 + q (loaded once)
    float w3x[4], w3y[4], w3z[4], w2r[4];
    #pragma unroll
    for (int q = 0; q < 4; q++) {
        int c = 4 * c4 + q;
        float s = gsv[c] * rsqrtf(vsv[c] + EPSV);
        w3x[q] = ws1[c * 67 + 0] * s;
        w3y[q] = ws1[c * 67 + 1] * s;
        w3z[q] = ws1[c * 67 + 2] * s;
        w2r[q] = ws2[c];
    }
    const float bias2 = bs2[0];

    // ---- phase 1: logit + exp + denom ----
    #pragma unroll 4
    for (int it = 0; it < 16; it++) {
        const int pidx = w * 32 + it * 2 + sub;            // 0..255
        const int mi = blockIdx.x * 256 + pidx;
        const int j  = mi >> 4;
        const int i  = knn[mi];
        float4 pq = g_p1q[i];
        float4 qq = g_p2q[j];
        float prx = pq.x - qq.x, pry = pq.y - qq.y, prz = pq.z - qq.z;

        float4 pv = *((const float4*)(g_pre + (size_t)j * 64) + c4);
        float part = 0.0f, h;
        h = fmaf(prx, w3x[0], fmaf(pry, w3y[0], fmaf(prz, w3z[0], pv.x)));
        part = fmaf(fmaxf(h, 0.f), w2r[0], part);
        h = fmaf(prx, w3x[1], fmaf(pry, w3y[1], fmaf(prz, w3z[1], pv.y)));
        part = fmaf(fmaxf(h, 0.f), w2r[1], part);
        h = fmaf(prx, w3x[2], fmaf(pry, w3y[2], fmaf(prz, w3z[2], pv.z)));
        part = fmaf(fmaxf(h, 0.f), w2r[2], part);
        h = fmaf(prx, w3x[3], fmaf(pry, w3y[3], fmaf(prz, w3z[3], pv.w)));
        part = fmaf(fmaxf(h, 0.f), w2r[3], part);

        // reduce across the 16 lanes of this pair
        part += __shfl_xor_sync(0xffffffffu, part, 1);
        part += __shfl_xor_sync(0xffffffffu, part, 2);
        part += __shfl_xor_sync(0xffffffffu, part, 4);
        part += __shfl_xor_sync(0xffffffffu, part, 8);

        if (c4 == 0) {
            float ev = __expf(part + bias2);
            se[pidx] = ev;
            si[pidx] = i;
            atomicAdd(&g_denom[i], ev);
        }
    }
    __syncthreads();

    // ---- phase 2: numerator scatter, 2 pairs per warp-iteration ----
    #pragma unroll
    for (int it = 0; it < 16; it++) {
        int pidx = w * 32 + it * 2 + sub;
        float e  = se[pidx];
        int   ii = si[pidx];
        int   jj = (blockIdx.x * 256 + pidx) >> 4;
        float4 u = *((const float4*)(g_upfeat + (size_t)jj * 64) + c4);
        float4 val = make_float4(u.x * e, u.y * e, u.z * e, u.w * e);
        atomicAdd((float4*)(g_acc + (size_t)ii * 64) + c4, val);
    }
}

extern "C" void kernel_launch(void* const* d_in, const int* in_sizes, int n_in,
                              void* d_out, int out_size)
{
    const float* p1  = (const float*)d_in[0];
    const float* p2  = (const float*)d_in[1];
    const float* x1  = (const float*)d_in[2];
    const float* x2  = (const float*)d_in[3];
    const int*   knn = (const int*)  d_in[4];
    const float* w1  = (const float*)d_in[5];
    const float* b1  = (const float*)d_in[6];
    const float* g1  = (const float*)d_in[7];
    const float* be1 = (const float*)d_in[8];
    const float* m1  = (const float*)d_in[9];
    const float* v1  = (const float*)d_in[10];
    const float* w2  = (const float*)d_in[11];
    const float* b2  = (const float*)d_in[12];
    const float* g2  = (const float*)d_in[13];
    const float* be2 = (const float*)d_in[14];
    const float* m2  = (const float*)d_in[15];
    const float* v2  = (const float*)d_in[16];
    const float* ws1 = (const float*)d_in[17];
    const float* bs1 = (const float*)d_in[18];
    const float* gs  = (const float*)d_in[19];
    const float* bes = (const float*)d_in[20];
    const float* ms  = (const float*)d_in[21];
    const float* vs  = (const float*)d_in[22];
    const float* ws2 = (const float*)d_in[23];
    const float* bs2 = (const float*)d_in[24];
    float* out = (float*)d_out;

    // zero acc/denom + pack p1/p2
    init_kernel<<<N1*16/256, 256>>>(p1, p2);
    // upfeat + pre (share x2 reads and A conversion)
    gemm_n2_kernel<<<444, 256>>>(x2, w2, b2, g2, be2, m2, v2,
                                 ws1, bs1, gs, bes, ms, vs);
    // fused logit + exp + denom + weighted numerator scatter
    pair_kernel<<<MPAIR/256, 256>>>(knn, ws1, gs, vs, ws2, bs2);
    // y1 GEMM + final normalize: out = relu(bn(x1@w1)) + acc/denom
    gemm_n1_kernel<<<444, 256>>>(x1, w1, b1, g1, be1, m1, v1, out);
}

// round 9
// speedup vs baseline: 1.3050x; 1.1410x over previous
#include <cuda_runtime.h>
#include <cuda_bf16.h>
#include <cstdint>

#define N1 262144
#define N2 65536
#define KNN 16
#define MPAIR (N2*KNN)
#define EPSV 1e-5f

// ---- static scratch (no runtime allocation allowed) ----
__device__ float  g_upfeat[N2*64];   // relu(bn(x2@w2^T))
__device__ float  g_pre[N2*64];      // x2-part of shrinker linear
__device__ float  g_e[MPAIR];        // exp(logit)
__device__ float  g_denom[N1];       // softmax denominator
__device__ float4 g_p1q[N1];         // packed p1 (xyz_)
__device__ float4 g_p2q[N2];         // packed p2 (xyz_)

// bf16 mma (baseline ISA, sm_80+; lowers to HMMA on sm_103 tensor pipe)
__device__ __forceinline__ void mma16816(float* d, const uint32_t* a, uint32_t b0, uint32_t b1) {
    asm volatile(
        "mma.sync.aligned.m16n8k16.row.col.f32.bf16.bf16.f32 "
        "{%0,%1,%2,%3}, {%4,%5,%6,%7}, {%8,%9}, {%0,%1,%2,%3};"
        : "+f"(d[0]), "+f"(d[1]), "+f"(d[2]), "+f"(d[3])
        : "r"(a[0]), "r"(a[1]), "r"(a[2]), "r"(a[3]), "r"(b0), "r"(b1));
}

__device__ __forceinline__ void split2(float f0, float f1, uint32_t& hi, uint32_t& lo) {
    __nv_bfloat16 h0 = __float2bfloat16_rn(f0);
    __nv_bfloat16 h1 = __float2bfloat16_rn(f1);
    __nv_bfloat162 hp; hp.x = h0; hp.y = h1;
    __nv_bfloat162 lp = __floats2bfloat162_rn(f0 - __bfloat162float(h0),
                                              f1 - __bfloat162float(h1));
    hi = *(uint32_t*)&hp;
    lo = *(uint32_t*)&lp;
}

// Pack BN-folded W into smem as bf16 hi/lo k-pairs in the k-permuted layout.
__device__ __forceinline__ void fill_packB(uint32_t* packB, float* fb,
                                           const float* __restrict__ w, int wstride, int wcol0,
                                           const float* __restrict__ bb,
                                           const float* __restrict__ gg,
                                           const float* __restrict__ be,
                                           const float* __restrict__ mm,
                                           const float* __restrict__ vv,
                                           int tid)
{
    if (tid < 64) {
        float s = gg[tid] * rsqrtf(vv[tid] + EPSV);
        fb[tid] = (bb[tid] - mm[tid]) * s + be[tid];
    }
    #pragma unroll
    for (int it = 0; it < 16; it++) {
        int idx = it * 256 + tid;
        int row = idx >> 6, col = idx & 63;
        int r31 = row & 31;
        int ks = r31 >> 3, q = r31 & 7;
        int kk = 16 * ks + ((q < 4) ? 4 * q : 4 * (q - 4) + 2);
        float s  = gg[col] * rsqrtf(vv[col] + EPSV);
        float w0 = w[col * wstride + wcol0 + kk]     * s;
        float w1 = w[col * wstride + wcol0 + kk + 1] * s;
        uint32_t hiw, low;
        split2(w0, w1, hiw, low);
        packB[row * 64 + (col ^ ((row & 3) << 3))] = (row < 32) ? hiw : low;
    }
}

__device__ __forceinline__ void load_A(const float* __restrict__ x, int m0, int gq, int tq,
                                       uint32_t Ah[4][4], uint32_t Al[4][4])
{
    const float4* r0 = (const float4*)(x + (size_t)(m0 + gq) * 64);
    const float4* r1 = (const float4*)(x + (size_t)(m0 + gq + 8) * 64);
    #pragma unroll
    for (int ks = 0; ks < 4; ks++) {
        float4 v0 = r0[4 * ks + tq];
        float4 v1 = r1[4 * ks + tq];
        split2(v0.x, v0.y, Ah[ks][0], Al[ks][0]);
        split2(v1.x, v1.y, Ah[ks][1], Al[ks][1]);
        split2(v0.z, v0.w, Ah[ks][2], Al[ks][2]);
        split2(v1.z, v1.w, Ah[ks][3], Al[ks][3]);
    }
}

// 3 accumulating chains over HALF the n-tiles (nt0..nt0+3): acc is 16 regs.
__device__ __forceinline__ void run_chains_half(float acc[4][4], const uint32_t* packB,
                                                const uint32_t Ah[4][4], const uint32_t Al[4][4],
                                                int gq, int tq, int nt0)
{
    const int csw = tq << 3;
    #pragma unroll
    for (int c = 0; c < 3; c++) {
        const uint32_t (*Af)[4] = (c == 2) ? Al : Ah;
        const int rb = (c == 1) ? 32 : 0;
        #pragma unroll
        for (int ks = 0; ks < 4; ks++) {
            const int r0i = (rb + 8 * ks + tq) * 64;
            const int r1i = (rb + 8 * ks + tq + 4) * 64;
            #pragma unroll
            for (int nt = 0; nt < 4; nt++) {
                int coff = (8 * (nt0 + nt) + gq) ^ csw;
                mma16816(acc[nt], Af[ks], packB[r0i + coff], packB[r1i + coff]);
            }
        }
    }
}

__device__ __forceinline__ void epilogue_half(float acc[4][4], const float* fb,
                                              float* __restrict__ o, int m0, int gq, int tq,
                                              int nt0, bool relu)
{
    float* o0 = o + (size_t)(m0 + gq) * 64;
    float* o1 = o + (size_t)(m0 + gq + 8) * 64;
    #pragma unroll
    for (int nt = 0; nt < 4; nt++) {
        int col = 8 * (nt0 + nt) + 2 * tq;
        float2 fbp = *(float2*)&fb[col];
        float2 u, v;
        u.x = acc[nt][0] + fbp.x; u.y = acc[nt][1] + fbp.y;
        v.x = acc[nt][2] + fbp.x; v.y = acc[nt][3] + fbp.y;
        if (relu) {
            u.x = fmaxf(u.x, 0.f); u.y = fmaxf(u.y, 0.f);
            v.x = fmaxf(v.x, 0.f); v.y = fmaxf(v.y, 0.f);
        }
        *(float2*)(o0 + col) = u;
        *(float2*)(o1 + col) = v;
    }
}

// ============ N1 GEMM (runs before scatter): out = relu(bn(x1@w1^T)) ============
__global__ void __launch_bounds__(256, 3)
gemm_n1_kernel(const float* __restrict__ x,
               const float* __restrict__ w,
               const float* __restrict__ bb, const float* __restrict__ gg,
               const float* __restrict__ be, const float* __restrict__ mm,
               const float* __restrict__ vv,
               float* __restrict__ outp)
{
    __shared__ uint32_t packB[64 * 64];
    __shared__ float fb[64];
    const int tid = threadIdx.x, wid = tid >> 5, lane = tid & 31;
    const int gq = lane >> 2, tq = lane & 3;

    fill_packB(packB, fb, w, 64, 0, bb, gg, be, mm, vv, tid);
    __syncthreads();

    for (int t = blockIdx.x; t < N1 / 128; t += gridDim.x) {
        const int m0 = t * 128 + wid * 16;
        uint32_t Ah[4][4], Al[4][4];
        load_A(x, m0, gq, tq, Ah, Al);

        #pragma unroll
        for (int half = 0; half < 2; half++) {
            float acc[4][4];
            #pragma unroll
            for (int nt = 0; nt < 4; nt++)
                #pragma unroll
                for (int r = 0; r < 4; r++) acc[nt][r] = 0.0f;
            run_chains_half(acc, packB, Ah, Al, gq, tq, half * 4);
            epilogue_half(acc, fb, outp, m0, gq, tq, half * 4, true);
        }
    }
}

// ====== N2 fused GEMM: upfeat + pre; tail packs p1/p2 and zeroes denom ======
__global__ void __launch_bounds__(256, 3)
gemm_n2_kernel(const float* __restrict__ x,
               const float* __restrict__ w2,
               const float* __restrict__ b2, const float* __restrict__ g2,
               const float* __restrict__ be2, const float* __restrict__ m2,
               const float* __restrict__ v2,
               const float* __restrict__ ws1,
               const float* __restrict__ bs1, const float* __restrict__ gs,
               const float* __restrict__ bes, const float* __restrict__ ms,
               const float* __restrict__ vs,
               const float* __restrict__ p1, const float* __restrict__ p2)
{
    __shared__ uint32_t packB2[64 * 64];
    __shared__ uint32_t packBs[64 * 64];
    __shared__ float fb2[64], fbs[64];
    const int tid = threadIdx.x, wid = tid >> 5, lane = tid & 31;
    const int gq = lane >> 2, tq = lane & 3;

    fill_packB(packB2, fb2, w2, 64, 0, b2, g2, be2, m2, v2, tid);
    fill_packB(packBs, fbs, ws1, 67, 3, bs1, gs, bes, ms, vs, tid);
    __syncthreads();

    for (int t = blockIdx.x; t < N2 / 128; t += gridDim.x) {
        const int m0 = t * 128 + wid * 16;
        uint32_t Ah[4][4], Al[4][4];
        load_A(x, m0, gq, tq, Ah, Al);

        #pragma unroll
        for (int half = 0; half < 2; half++) {
            float acc[4][4];
            #pragma unroll
            for (int nt = 0; nt < 4; nt++)
                #pragma unroll
                for (int r = 0; r < 4; r++) acc[nt][r] = 0.0f;
            run_chains_half(acc, packB2, Ah, Al, gq, tq, half * 4);
            epilogue_half(acc, fb2, g_upfeat, m0, gq, tq, half * 4, true);

            #pragma unroll
            for (int nt = 0; nt < 4; nt++)
                #pragma unroll
                for (int r = 0; r < 4; r++) acc[nt][r] = 0.0f;
            run_chains_half(acc, packBs, Ah, Al, gq, tq, half * 4);
            epilogue_half(acc, fbs, g_pre, m0, gq, tq, half * 4, false);
        }
    }

    // ---- tail: zero denom + pack p1/p2 (grid-stride) ----
    const int gt = blockIdx.x * 256 + tid;
    const int nthreads = gridDim.x * 256;
    for (int i = gt; i < N1; i += nthreads) {
        g_denom[i] = 0.0f;
        g_p1q[i] = make_float4(p1[3*i], p1[3*i+1], p1[3*i+2], 0.f);
    }
    for (int i = gt; i < N2; i += nthreads)
        g_p2q[i] = make_float4(p2[3*i], p2[3*i+1], p2[3*i+2], 0.f);
}

// ===================== logit + exp + denom (thread per pair, R6-proven) =====================
__global__ void __launch_bounds__(256)
logit_kernel(const int*   __restrict__ knn,
             const float* __restrict__ ws1,
             const float* __restrict__ gsv,
             const float* __restrict__ vsv,
             const float* __restrict__ ws2,
             const float* __restrict__ bs2)
{
    __shared__ float sw3[64][3];
    __shared__ float sw2[64];
    const int tid = threadIdx.x;
    if (tid < 64) {
        float s = gsv[tid] * rsqrtf(vsv[tid] + EPSV);
        sw3[tid][0] = ws1[tid * 67 + 0] * s;
        sw3[tid][1] = ws1[tid * 67 + 1] * s;
        sw3[tid][2] = ws1[tid * 67 + 2] * s;
        sw2[tid]    = ws2[tid];
    }
    __syncthreads();

    const int mi = blockIdx.x * 256 + tid;
    const int j  = mi >> 4;
    const int i  = knn[mi];
    float4 pq = g_p1q[i];
    float4 qq = g_p2q[j];
    float prx = pq.x - qq.x, pry = pq.y - qq.y, prz = pq.z - qq.z;

    float acc = 0.0f;
    const float4* pre4 = (const float4*)(g_pre + (size_t)j * 64);
    #pragma unroll
    for (int c4 = 0; c4 < 16; c4++) {
        float4 pv = pre4[c4];
        int c = c4 * 4;
        float h;
        h = fmaf(prx, sw3[c+0][0], fmaf(pry, sw3[c+0][1], fmaf(prz, sw3[c+0][2], pv.x)));
        h = fmaxf(h, 0.0f); acc = fmaf(h, sw2[c+0], acc);
        h = fmaf(prx, sw3[c+1][0], fmaf(pry, sw3[c+1][1], fmaf(prz, sw3[c+1][2], pv.y)));
        h = fmaxf(h, 0.0f); acc = fmaf(h, sw2[c+1], acc);
        h = fmaf(prx, sw3[c+2][0], fmaf(pry, sw3[c+2][1], fmaf(prz, sw3[c+2][2], pv.z)));
        h = fmaxf(h, 0.0f); acc = fmaf(h, sw2[c+2], acc);
        h = fmaf(prx, sw3[c+3][0], fmaf(pry, sw3[c+3][1], fmaf(prz, sw3[c+3][2], pv.w)));
        h = fmaxf(h, 0.0f); acc = fmaf(h, sw2[c+3], acc);
    }
    float ev = __expf(acc + bs2[0]);
    g_e[mi] = ev;
    atomicAdd(&g_denom[i], ev);
}

// ========= prob-weighted scatter into out: 16 lanes per pair, float4 RED.128 =========
__global__ void __launch_bounds__(256)
scatter_kernel(const int* __restrict__ knn, float* __restrict__ out)
{
    const int tid  = threadIdx.x;
    const int lane = tid & 31, w = tid >> 5;
    const int sub  = lane >> 4;        // which of 2 pairs this iteration
    const int c4   = lane & 15;        // float4 channel group within pair

    #pragma unroll
    for (int it = 0; it < 16; it++) {
        const int pidx = w * 32 + it * 2 + sub;           // 0..255
        const int mi = blockIdx.x * 256 + pidx;
        const int j  = mi >> 4;
        const int i  = knn[mi];
        float dn = g_denom[i];
        float prob = g_e[mi] * (dn > 0.f ? 1.0f / dn : 0.0f);
        float4 u = *((const float4*)(g_upfeat + (size_t)j * 64) + c4);
        float4 val = make_float4(u.x * prob, u.y * prob, u.z * prob, u.w * prob);
        atomicAdd((float4*)(out + (size_t)i * 64) + c4, val);
    }
}

extern "C" void kernel_launch(void* const* d_in, const int* in_sizes, int n_in,
                              void* d_out, int out_size)
{
    const float* p1  = (const float*)d_in[0];
    const float* p2  = (const float*)d_in[1];
    const float* x1  = (const float*)d_in[2];
    const float* x2  = (const float*)d_in[3];
    const int*   knn = (const int*)  d_in[4];
    const float* w1  = (const float*)d_in[5];
    const float* b1  = (const float*)d_in[6];
    const float* g1  = (const float*)d_in[7];
    const float* be1 = (const float*)d_in[8];
    const float* m1  = (const float*)d_in[9];
    const float* v1  = (const float*)d_in[10];
    const float* w2  = (const float*)d_in[11];
    const float* b2  = (const float*)d_in[12];
    const float* g2  = (const float*)d_in[13];
    const float* be2 = (const float*)d_in[14];
    const float* m2  = (const float*)d_in[15];
    const float* v2  = (const float*)d_in[16];
    const float* ws1 = (const float*)d_in[17];
    const float* bs1 = (const float*)d_in[18];
    const float* gs  = (const float*)d_in[19];
    const float* bes = (const float*)d_in[20];
    const float* ms  = (const float*)d_in[21];
    const float* vs  = (const float*)d_in[22];
    const float* ws2 = (const float*)d_in[23];
    const float* bs2 = (const float*)d_in[24];
    float* out = (float*)d_out;

    // upfeat + pre GEMMs; tail zeroes denom and packs p1/p2
    gemm_n2_kernel<<<444, 256>>>(x2, w2, b2, g2, be2, m2, v2,
                                 ws1, bs1, gs, bes, ms, vs, p1, p2);
    // y1 -> out (initializes every output element)
    gemm_n1_kernel<<<444, 256>>>(x1, w1, b1, g1, be1, m1, v1, out);
    // logit + exp + denom
    logit_kernel<<<MPAIR/256, 256>>>(knn, ws1, gs, vs, ws2, bs2);
    // prob-weighted scatter on top of y1
    scatter_kernel<<<MPAIR/256, 256>>>(knn, out);
}

// round 10
// speedup vs baseline: 1.3234x; 1.0141x over previous
#include <cuda_runtime.h>
#include <cuda_bf16.h>
#include <cstdint>

#define N1 262144
#define N2 65536
#define KNN 16
#define MPAIR (N2*KNN)
#define EPSV 1e-5f

#define FUSED_BLOCKS 444
#define N1_BLOCKS 260
#define LOGIT_BLOCKS (FUSED_BLOCKS - N1_BLOCKS)

// ---- static scratch (no runtime allocation allowed) ----
__device__ float  g_upfeat[N2*64];   // relu(bn(x2@w2^T))
__device__ float  g_pre[N2*64];      // x2-part of shrinker linear
__device__ float  g_e[MPAIR];        // exp(logit)
__device__ float  g_denom[N1];       // softmax denominator
__device__ float4 g_p1q[N1];         // packed p1 (xyz_)
__device__ float4 g_p2q[N2];         // packed p2 (xyz_)

// bf16 mma (baseline ISA, sm_80+; lowers to HMMA on sm_103 tensor pipe)
__device__ __forceinline__ void mma16816(float* d, const uint32_t* a, uint32_t b0, uint32_t b1) {
    asm volatile(
        "mma.sync.aligned.m16n8k16.row.col.f32.bf16.bf16.f32 "
        "{%0,%1,%2,%3}, {%4,%5,%6,%7}, {%8,%9}, {%0,%1,%2,%3};"
        : "+f"(d[0]), "+f"(d[1]), "+f"(d[2]), "+f"(d[3])
        : "r"(a[0]), "r"(a[1]), "r"(a[2]), "r"(a[3]), "r"(b0), "r"(b1));
}

__device__ __forceinline__ void split2(float f0, float f1, uint32_t& hi, uint32_t& lo) {
    __nv_bfloat16 h0 = __float2bfloat16_rn(f0);
    __nv_bfloat16 h1 = __float2bfloat16_rn(f1);
    __nv_bfloat162 hp; hp.x = h0; hp.y = h1;
    __nv_bfloat162 lp = __floats2bfloat162_rn(f0 - __bfloat162float(h0),
                                              f1 - __bfloat162float(h1));
    hi = *(uint32_t*)&hp;
    lo = *(uint32_t*)&lp;
}

// Pack BN-folded W into smem as bf16 hi/lo k-pairs in the k-permuted layout.
__device__ __forceinline__ void fill_packB(uint32_t* packB, float* fb,
                                           const float* __restrict__ w, int wstride, int wcol0,
                                           const float* __restrict__ bb,
                                           const float* __restrict__ gg,
                                           const float* __restrict__ be,
                                           const float* __restrict__ mm,
                                           const float* __restrict__ vv,
                                           int tid)
{
    if (tid < 64) {
        float s = gg[tid] * rsqrtf(vv[tid] + EPSV);
        fb[tid] = (bb[tid] - mm[tid]) * s + be[tid];
    }
    #pragma unroll
    for (int it = 0; it < 16; it++) {
        int idx = it * 256 + tid;
        int row = idx >> 6, col = idx & 63;
        int r31 = row & 31;
        int ks = r31 >> 3, q = r31 & 7;
        int kk = 16 * ks + ((q < 4) ? 4 * q : 4 * (q - 4) + 2);
        float s  = gg[col] * rsqrtf(vv[col] + EPSV);
        float w0 = w[col * wstride + wcol0 + kk]     * s;
        float w1 = w[col * wstride + wcol0 + kk + 1] * s;
        uint32_t hiw, low;
        split2(w0, w1, hiw, low);
        packB[row * 64 + (col ^ ((row & 3) << 3))] = (row < 32) ? hiw : low;
    }
}

__device__ __forceinline__ void load_A(const float* __restrict__ x, int m0, int gq, int tq,
                                       uint32_t Ah[4][4], uint32_t Al[4][4])
{
    const float4* r0 = (const float4*)(x + (size_t)(m0 + gq) * 64);
    const float4* r1 = (const float4*)(x + (size_t)(m0 + gq + 8) * 64);
    #pragma unroll
    for (int ks = 0; ks < 4; ks++) {
        float4 v0 = r0[4 * ks + tq];
        float4 v1 = r1[4 * ks + tq];
        split2(v0.x, v0.y, Ah[ks][0], Al[ks][0]);
        split2(v1.x, v1.y, Ah[ks][1], Al[ks][1]);
        split2(v0.z, v0.w, Ah[ks][2], Al[ks][2]);
        split2(v1.z, v1.w, Ah[ks][3], Al[ks][3]);
    }
}

// 3 accumulating chains over HALF the n-tiles (nt0..nt0+3): acc is 16 regs.
__device__ __forceinline__ void run_chains_half(float acc[4][4], const uint32_t* packB,
                                                const uint32_t Ah[4][4], const uint32_t Al[4][4],
                                                int gq, int tq, int nt0)
{
    const int csw = tq << 3;
    #pragma unroll
    for (int c = 0; c < 3; c++) {
        const uint32_t (*Af)[4] = (c == 2) ? Al : Ah;
        const int rb = (c == 1) ? 32 : 0;
        #pragma unroll
        for (int ks = 0; ks < 4; ks++) {
            const int r0i = (rb + 8 * ks + tq) * 64;
            const int r1i = (rb + 8 * ks + tq + 4) * 64;
            #pragma unroll
            for (int nt = 0; nt < 4; nt++) {
                int coff = (8 * (nt0 + nt) + gq) ^ csw;
                mma16816(acc[nt], Af[ks], packB[r0i + coff], packB[r1i + coff]);
            }
        }
    }
}

__device__ __forceinline__ void epilogue_half(float acc[4][4], const float* fb,
                                              float* __restrict__ o, int m0, int gq, int tq,
                                              int nt0, bool relu)
{
    float* o0 = o + (size_t)(m0 + gq) * 64;
    float* o1 = o + (size_t)(m0 + gq + 8) * 64;
    #pragma unroll
    for (int nt = 0; nt < 4; nt++) {
        int col = 8 * (nt0 + nt) + 2 * tq;
        float2 fbp = *(float2*)&fb[col];
        float2 u, v;
        u.x = acc[nt][0] + fbp.x; u.y = acc[nt][1] + fbp.y;
        v.x = acc[nt][2] + fbp.x; v.y = acc[nt][3] + fbp.y;
        if (relu) {
            u.x = fmaxf(u.x, 0.f); u.y = fmaxf(u.y, 0.f);
            v.x = fmaxf(v.x, 0.f); v.y = fmaxf(v.y, 0.f);
        }
        *(float2*)(o0 + col) = u;
        *(float2*)(o1 + col) = v;
    }
}

// ====== N2 fused GEMM: upfeat + pre; tail packs p1/p2 and zeroes denom ======
__global__ void __launch_bounds__(256, 3)
gemm_n2_kernel(const float* __restrict__ x,
               const float* __restrict__ w2,
               const float* __restrict__ b2, const float* __restrict__ g2,
               const float* __restrict__ be2, const float* __restrict__ m2,
               const float* __restrict__ v2,
               const float* __restrict__ ws1,
               const float* __restrict__ bs1, const float* __restrict__ gs,
               const float* __restrict__ bes, const float* __restrict__ ms,
               const float* __restrict__ vs,
               const float* __restrict__ p1, const float* __restrict__ p2)
{
    __shared__ uint32_t packB2[64 * 64];
    __shared__ uint32_t packBs[64 * 64];
    __shared__ float fb2[64], fbs[64];
    const int tid = threadIdx.x, wid = tid >> 5, lane = tid & 31;
    const int gq = lane >> 2, tq = lane & 3;

    fill_packB(packB2, fb2, w2, 64, 0, b2, g2, be2, m2, v2, tid);
    fill_packB(packBs, fbs, ws1, 67, 3, bs1, gs, bes, ms, vs, tid);
    __syncthreads();

    for (int t = blockIdx.x; t < N2 / 128; t += gridDim.x) {
        const int m0 = t * 128 + wid * 16;
        uint32_t Ah[4][4], Al[4][4];
        load_A(x, m0, gq, tq, Ah, Al);

        #pragma unroll
        for (int half = 0; half < 2; half++) {
            float acc[4][4];
            #pragma unroll
            for (int nt = 0; nt < 4; nt++)
                #pragma unroll
                for (int r = 0; r < 4; r++) acc[nt][r] = 0.0f;
            run_chains_half(acc, packB2, Ah, Al, gq, tq, half * 4);
            epilogue_half(acc, fb2, g_upfeat, m0, gq, tq, half * 4, true);

            #pragma unroll
            for (int nt = 0; nt < 4; nt++)
                #pragma unroll
                for (int r = 0; r < 4; r++) acc[nt][r] = 0.0f;
            run_chains_half(acc, packBs, Ah, Al, gq, tq, half * 4);
            epilogue_half(acc, fbs, g_pre, m0, gq, tq, half * 4, false);
        }
    }

    // ---- tail: zero denom + pack p1/p2 (grid-stride) ----
    const int gt = blockIdx.x * 256 + tid;
    const int nthreads = gridDim.x * 256;
    for (int i = gt; i < N1; i += nthreads) {
        g_denom[i] = 0.0f;
        g_p1q[i] = make_float4(p1[3*i], p1[3*i+1], p1[3*i+2], 0.f);
    }
    for (int i = gt; i < N2; i += nthreads)
        g_p2q[i] = make_float4(p2[3*i], p2[3*i+1], p2[3*i+2], 0.f);
}

// ============ FUSED: blocks [0,N1_BLOCKS) do the N1 GEMM (out = relu(bn(x1@w1^T)));
// ============ blocks [N1_BLOCKS,444) do logit+exp+denom over all pairs.
// The two legs are independent; co-residency fills each other's latency bubbles.
__global__ void __launch_bounds__(256, 3)
fused_n1_logit_kernel(const float* __restrict__ x,
                      const float* __restrict__ w,
                      const float* __restrict__ bb, const float* __restrict__ gg,
                      const float* __restrict__ be, const float* __restrict__ mm,
                      const float* __restrict__ vv,
                      float* __restrict__ outp,
                      const int*   __restrict__ knn,
                      const float* __restrict__ ws1,
                      const float* __restrict__ gsv,
                      const float* __restrict__ vsv,
                      const float* __restrict__ ws2,
                      const float* __restrict__ bs2)
{
    __shared__ uint32_t smem_u[64 * 64];     // n1: packB; logit: unused bulk
    __shared__ float    smem_f[64 * 4];      // n1: fb; logit: sw3[64][3] + sw2[64]
    const int tid = threadIdx.x;

    if (blockIdx.x < N1_BLOCKS) {
        // ------------------- N1 GEMM leg -------------------
        uint32_t* packB = smem_u;
        float* fb = smem_f;
        const int wid = tid >> 5, lane = tid & 31;
        const int gq = lane >> 2, tq = lane & 3;

        fill_packB(packB, fb, w, 64, 0, bb, gg, be, mm, vv, tid);
        __syncthreads();

        for (int t = blockIdx.x; t < N1 / 128; t += N1_BLOCKS) {
            const int m0 = t * 128 + wid * 16;
            uint32_t Ah[4][4], Al[4][4];
            load_A(x, m0, gq, tq, Ah, Al);

            #pragma unroll
            for (int half = 0; half < 2; half++) {
                float acc[4][4];
                #pragma unroll
                for (int nt = 0; nt < 4; nt++)
                    #pragma unroll
                    for (int r = 0; r < 4; r++) acc[nt][r] = 0.0f;
                run_chains_half(acc, packB, Ah, Al, gq, tq, half * 4);
                epilogue_half(acc, fb, outp, m0, gq, tq, half * 4, true);
            }
        }
    } else {
        // ------------------- logit leg -------------------
        float (*sw3)[3] = (float(*)[3])smem_f;          // 64*3 floats
        float* sw2 = smem_f + 192;                      // 64 floats
        if (tid < 64) {
            float s = gsv[tid] * rsqrtf(vsv[tid] + EPSV);
            sw3[tid][0] = ws1[tid * 67 + 0] * s;
            sw3[tid][1] = ws1[tid * 67 + 1] * s;
            sw3[tid][2] = ws1[tid * 67 + 2] * s;
            sw2[tid]    = ws2[tid];
        }
        __syncthreads();
        const float bias2 = bs2[0];

        for (int u = blockIdx.x - N1_BLOCKS; u < MPAIR / 256; u += LOGIT_BLOCKS) {
            const int mi = u * 256 + tid;
            const int j  = mi >> 4;
            const int i  = knn[mi];
            float4 pq = g_p1q[i];
            float4 qq = g_p2q[j];
            float prx = pq.x - qq.x, pry = pq.y - qq.y, prz = pq.z - qq.z;

            float acc = 0.0f;
            const float4* pre4 = (const float4*)(g_pre + (size_t)j * 64);
            #pragma unroll
            for (int c4 = 0; c4 < 16; c4++) {
                float4 pv = pre4[c4];
                int c = c4 * 4;
                float h;
                h = fmaf(prx, sw3[c+0][0], fmaf(pry, sw3[c+0][1], fmaf(prz, sw3[c+0][2], pv.x)));
                h = fmaxf(h, 0.0f); acc = fmaf(h, sw2[c+0], acc);
                h = fmaf(prx, sw3[c+1][0], fmaf(pry, sw3[c+1][1], fmaf(prz, sw3[c+1][2], pv.y)));
                h = fmaxf(h, 0.0f); acc = fmaf(h, sw2[c+1], acc);
                h = fmaf(prx, sw3[c+2][0], fmaf(pry, sw3[c+2][1], fmaf(prz, sw3[c+2][2], pv.z)));
                h = fmaxf(h, 0.0f); acc = fmaf(h, sw2[c+2], acc);
                h = fmaf(prx, sw3[c+3][0], fmaf(pry, sw3[c+3][1], fmaf(prz, sw3[c+3][2], pv.w)));
                h = fmaxf(h, 0.0f); acc = fmaf(h, sw2[c+3], acc);
            }
            float ev = __expf(acc + bias2);
            g_e[mi] = ev;
            atomicAdd(&g_denom[i], ev);
        }
    }
}

// ========= prob-weighted scatter into out: 16 lanes per pair, float4 RED.128 =========
__global__ void __launch_bounds__(256)
scatter_kernel(const int* __restrict__ knn, float* __restrict__ out)
{
    const int tid  = threadIdx.x;
    const int lane = tid & 31, w = tid >> 5;
    const int sub  = lane >> 4;        // which of 2 pairs this iteration
    const int c4   = lane & 15;        // float4 channel group within pair

    #pragma unroll
    for (int it = 0; it < 16; it++) {
        const int pidx = w * 32 + it * 2 + sub;           // 0..255
        const int mi = blockIdx.x * 256 + pidx;
        const int j  = mi >> 4;
        const int i  = knn[mi];
        float dn = g_denom[i];
        float prob = g_e[mi] * (dn > 0.f ? 1.0f / dn : 0.0f);
        float4 u = *((const float4*)(g_upfeat + (size_t)j * 64) + c4);
        float4 val = make_float4(u.x * prob, u.y * prob, u.z * prob, u.w * prob);
        atomicAdd((float4*)(out + (size_t)i * 64) + c4, val);
    }
}

extern "C" void kernel_launch(void* const* d_in, const int* in_sizes, int n_in,
                              void* d_out, int out_size)
{
    const float* p1  = (const float*)d_in[0];
    const float* p2  = (const float*)d_in[1];
    const float* x1  = (const float*)d_in[2];
    const float* x2  = (const float*)d_in[3];
    const int*   knn = (const int*)  d_in[4];
    const float* w1  = (const float*)d_in[5];
    const float* b1  = (const float*)d_in[6];
    const float* g1  = (const float*)d_in[7];
    const float* be1 = (const float*)d_in[8];
    const float* m1  = (const float*)d_in[9];
    const float* v1  = (const float*)d_in[10];
    const float* w2  = (const float*)d_in[11];
    const float* b2  = (const float*)d_in[12];
    const float* g2  = (const float*)d_in[13];
    const float* be2 = (const float*)d_in[14];
    const float* m2  = (const float*)d_in[15];
    const float* v2  = (const float*)d_in[16];
    const float* ws1 = (const float*)d_in[17];
    const float* bs1 = (const float*)d_in[18];
    const float* gs  = (const float*)d_in[19];
    const float* bes = (const float*)d_in[20];
    const float* ms  = (const float*)d_in[21];
    const float* vs  = (const float*)d_in[22];
    const float* ws2 = (const float*)d_in[23];
    const float* bs2 = (const float*)d_in[24];
    float* out = (float*)d_out;

    // upfeat + pre GEMMs; tail zeroes denom and packs p1/p2
    gemm_n2_kernel<<<444, 256>>>(x2, w2, b2, g2, be2, m2, v2,
                                 ws1, bs1, gs, bes, ms, vs, p1, p2);
    // y1 -> out  CONCURRENT WITH  logit+exp+denom (block-partitioned fusion)
    fused_n1_logit_kernel<<<FUSED_BLOCKS, 256>>>(x1, w1, b1, g1, be1, m1, v1, out,
                                                 knn, ws1, gs, vs, ws2, bs2);
    // prob-weighted scatter on top of y1
    scatter_kernel<<<MPAIR/256, 256>>>(knn, out);
}

// round 11
// speedup vs baseline: 1.4149x; 1.0691x over previous
#include <cuda_runtime.h>
#include <cuda_bf16.h>
#include <cstdint>

#define N1 262144
#define N2 65536
#define KNN 16
#define MPAIR (N2*KNN)
#define EPSV 1e-5f

#define FUSED_BLOCKS 444
#define N1_BLOCKS 280
#define LOGIT_BLOCKS (FUSED_BLOCKS - N1_BLOCKS)

// ---- static scratch (no runtime allocation allowed) ----
__device__ float    g_upfeat[N2*64];   // relu(bn(x2@w2^T))
__device__ float    g_pre[N2*64];      // x2-part of shrinker linear
__device__ float    g_e[MPAIR];        // exp(logit)
__device__ float    g_denom[N1];       // softmax denominator
__device__ float4   g_p1q[N1];         // packed p1 (xyz_)
__device__ float4   g_p2q[N2];         // packed p2 (xyz_)
__device__ uint32_t g_packW[3*4096];   // prepacked+swizzled bf16 hi/lo weights (w1,w2,ws1)
__device__ float    g_fbW[3*64];       // folded biases
__device__ float4   g_sw34[64];        // shrinker (w3x,w3y,w3z,w2) per channel

// bf16 mma (baseline ISA, sm_80+; lowers to HMMA on sm_103 tensor pipe)
__device__ __forceinline__ void mma16816(float* d, const uint32_t* a, uint32_t b0, uint32_t b1) {
    asm volatile(
        "mma.sync.aligned.m16n8k16.row.col.f32.bf16.bf16.f32 "
        "{%0,%1,%2,%3}, {%4,%5,%6,%7}, {%8,%9}, {%0,%1,%2,%3};"
        : "+f"(d[0]), "+f"(d[1]), "+f"(d[2]), "+f"(d[3])
        : "r"(a[0]), "r"(a[1]), "r"(a[2]), "r"(a[3]), "r"(b0), "r"(b1));
}

__device__ __forceinline__ void split2(float f0, float f1, uint32_t& hi, uint32_t& lo) {
    __nv_bfloat16 h0 = __float2bfloat16_rn(f0);
    __nv_bfloat16 h1 = __float2bfloat16_rn(f1);
    __nv_bfloat162 hp; hp.x = h0; hp.y = h1;
    __nv_bfloat162 lp = __floats2bfloat162_rn(f0 - __bfloat162float(h0),
                                              f1 - __bfloat162float(h1));
    hi = *(uint32_t*)&hp;
    lo = *(uint32_t*)&lp;
}

// ============ prep: pack all weights once + folded biases + sw34 + init ============
__global__ void __launch_bounds__(256)
prep_kernel(const float* __restrict__ w1, const float* __restrict__ b1,
            const float* __restrict__ g1, const float* __restrict__ be1,
            const float* __restrict__ m1, const float* __restrict__ v1,
            const float* __restrict__ w2, const float* __restrict__ b2,
            const float* __restrict__ g2, const float* __restrict__ be2,
            const float* __restrict__ m2, const float* __restrict__ v2,
            const float* __restrict__ ws1, const float* __restrict__ bs1,
            const float* __restrict__ gs, const float* __restrict__ bes,
            const float* __restrict__ ms, const float* __restrict__ vs,
            const float* __restrict__ ws2,
            const float* __restrict__ p1, const float* __restrict__ p2)
{
    const int gid = blockIdx.x * 256 + threadIdx.x;

    if (gid < 3 * 4096) {
        // weight packing in the k-permuted swizzled layout (same math as old fill_packB)
        int mat = gid >> 12, idx = gid & 4095;
        const float *w, *gg, *vv; int wstride, wcol0;
        if (mat == 0)      { w = w1;  gg = g1; vv = v1; wstride = 64; wcol0 = 0; }
        else if (mat == 1) { w = w2;  gg = g2; vv = v2; wstride = 64; wcol0 = 0; }
        else               { w = ws1; gg = gs; vv = vs; wstride = 67; wcol0 = 3; }
        int row = idx >> 6, col = idx & 63;
        int r31 = row & 31;
        int ks = r31 >> 3, q = r31 & 7;
        int kk = 16 * ks + ((q < 4) ? 4 * q : 4 * (q - 4) + 2);
        float s  = gg[col] * rsqrtf(vv[col] + EPSV);
        float w0 = w[col * wstride + wcol0 + kk]     * s;
        float wv = w[col * wstride + wcol0 + kk + 1] * s;
        uint32_t hiw, low;
        split2(w0, wv, hiw, low);
        g_packW[mat * 4096 + row * 64 + (col ^ ((row & 3) << 3))] = (row < 32) ? hiw : low;
    } else if (gid < 3 * 4096 + 192) {
        int t = gid - 3 * 4096; int mat = t >> 6, c = t & 63;
        const float *bb, *gg, *be, *mm, *vv;
        if (mat == 0)      { bb = b1;  gg = g1; be = be1; mm = m1; vv = v1; }
        else if (mat == 1) { bb = b2;  gg = g2; be = be2; mm = m2; vv = v2; }
        else               { bb = bs1; gg = gs; be = bes; mm = ms; vv = vs; }
        float s = gg[c] * rsqrtf(vv[c] + EPSV);
        g_fbW[mat * 64 + c] = (bb[c] - mm[c]) * s + be[c];
    } else if (gid < 3 * 4096 + 192 + 64) {
        int c = gid - (3 * 4096 + 192);
        float s = gs[c] * rsqrtf(vs[c] + EPSV);
        g_sw34[c] = make_float4(ws1[c * 67] * s, ws1[c * 67 + 1] * s,
                                ws1[c * 67 + 2] * s, ws2[c]);
    }

    const int tot = gridDim.x * 256;
    for (int i = gid; i < N1; i += tot) {
        g_denom[i] = 0.0f;
        g_p1q[i] = make_float4(p1[3*i], p1[3*i+1], p1[3*i+2], 0.f);
    }
    for (int i = gid; i < N2; i += tot)
        g_p2q[i] = make_float4(p2[3*i], p2[3*i+1], p2[3*i+2], 0.f);
}

// fast smem fill from prepacked global: 16KB coalesced copy + bias
__device__ __forceinline__ void fill_fast(uint32_t* packB, float* fb, int mat, int tid) {
    const float4* src = (const float4*)(g_packW + mat * 4096);
    #pragma unroll
    for (int it = 0; it < 4; it++)
        ((float4*)packB)[it * 256 + tid] = src[it * 256 + tid];
    if (tid < 64) fb[tid] = g_fbW[mat * 64 + tid];
}

__device__ __forceinline__ void load_A(const float* __restrict__ x, int m0, int gq, int tq,
                                       uint32_t Ah[4][4], uint32_t Al[4][4])
{
    const float4* r0 = (const float4*)(x + (size_t)(m0 + gq) * 64);
    const float4* r1 = (const float4*)(x + (size_t)(m0 + gq + 8) * 64);
    #pragma unroll
    for (int ks = 0; ks < 4; ks++) {
        float4 v0 = r0[4 * ks + tq];
        float4 v1 = r1[4 * ks + tq];
        split2(v0.x, v0.y, Ah[ks][0], Al[ks][0]);
        split2(v1.x, v1.y, Ah[ks][1], Al[ks][1]);
        split2(v0.z, v0.w, Ah[ks][2], Al[ks][2]);
        split2(v1.z, v1.w, Ah[ks][3], Al[ks][3]);
    }
}

// 3 accumulating chains over HALF the n-tiles (nt0..nt0+3): acc is 16 regs.
__device__ __forceinline__ void run_chains_half(float acc[4][4], const uint32_t* packB,
                                                const uint32_t Ah[4][4], const uint32_t Al[4][4],
                                                int gq, int tq, int nt0)
{
    const int csw = tq << 3;
    #pragma unroll
    for (int c = 0; c < 3; c++) {
        const uint32_t (*Af)[4] = (c == 2) ? Al : Ah;
        const int rb = (c == 1) ? 32 : 0;
        #pragma unroll
        for (int ks = 0; ks < 4; ks++) {
            const int r0i = (rb + 8 * ks + tq) * 64;
            const int r1i = (rb + 8 * ks + tq + 4) * 64;
            #pragma unroll
            for (int nt = 0; nt < 4; nt++) {
                int coff = (8 * (nt0 + nt) + gq) ^ csw;
                mma16816(acc[nt], Af[ks], packB[r0i + coff], packB[r1i + coff]);
            }
        }
    }
}

__device__ __forceinline__ void epilogue_half(float acc[4][4], const float* fb,
                                              float* __restrict__ o, int m0, int gq, int tq,
                                              int nt0, bool relu)
{
    float* o0 = o + (size_t)(m0 + gq) * 64;
    float* o1 = o + (size_t)(m0 + gq + 8) * 64;
    #pragma unroll
    for (int nt = 0; nt < 4; nt++) {
        int col = 8 * (nt0 + nt) + 2 * tq;
        float2 fbp = *(float2*)&fb[col];
        float2 u, v;
        u.x = acc[nt][0] + fbp.x; u.y = acc[nt][1] + fbp.y;
        v.x = acc[nt][2] + fbp.x; v.y = acc[nt][3] + fbp.y;
        if (relu) {
            u.x = fmaxf(u.x, 0.f); u.y = fmaxf(u.y, 0.f);
            v.x = fmaxf(v.x, 0.f); v.y = fmaxf(v.y, 0.f);
        }
        *(float2*)(o0 + col) = u;
        *(float2*)(o1 + col) = v;
    }
}

// ====== N2 fused GEMM: upfeat (w2, relu) + pre (ws1[:,3:], no relu) ======
__global__ void __launch_bounds__(256, 3)
gemm_n2_kernel(const float* __restrict__ x)
{
    __shared__ uint32_t packB2[64 * 64];
    __shared__ uint32_t packBs[64 * 64];
    __shared__ float fb2[64], fbs[64];
    const int tid = threadIdx.x, wid = tid >> 5, lane = tid & 31;
    const int gq = lane >> 2, tq = lane & 3;

    fill_fast(packB2, fb2, 1, tid);
    fill_fast(packBs, fbs, 2, tid);
    __syncthreads();

    for (int t = blockIdx.x; t < N2 / 128; t += gridDim.x) {
        const int m0 = t * 128 + wid * 16;
        uint32_t Ah[4][4], Al[4][4];
        load_A(x, m0, gq, tq, Ah, Al);

        #pragma unroll
        for (int half = 0; half < 2; half++) {
            float acc[4][4];
            #pragma unroll
            for (int nt = 0; nt < 4; nt++)
                #pragma unroll
                for (int r = 0; r < 4; r++) acc[nt][r] = 0.0f;
            run_chains_half(acc, packB2, Ah, Al, gq, tq, half * 4);
            epilogue_half(acc, fb2, g_upfeat, m0, gq, tq, half * 4, true);

            #pragma unroll
            for (int nt = 0; nt < 4; nt++)
                #pragma unroll
                for (int r = 0; r < 4; r++) acc[nt][r] = 0.0f;
            run_chains_half(acc, packBs, Ah, Al, gq, tq, half * 4);
            epilogue_half(acc, fbs, g_pre, m0, gq, tq, half * 4, false);
        }
    }
}

// ============ FUSED: blocks [0,N1_BLOCKS) do N1 GEMM; rest do logit+exp+denom ============
__global__ void __launch_bounds__(256, 3)
fused_n1_logit_kernel(const float* __restrict__ x,
                      float* __restrict__ outp,
                      const int*   __restrict__ knn,
                      const float* __restrict__ bs2)
{
    __shared__ uint32_t smem_u[64 * 64];     // n1: packB
    __shared__ float4   smem_q[64];          // logit: sw34
    __shared__ float    smem_f[64];          // n1: fb
    const int tid = threadIdx.x;

    if (blockIdx.x < N1_BLOCKS) {
        // ------------------- N1 GEMM leg: out = relu(bn(x1@w1^T)) -------------------
        const int wid = tid >> 5, lane = tid & 31;
        const int gq = lane >> 2, tq = lane & 3;

        fill_fast(smem_u, smem_f, 0, tid);
        __syncthreads();

        for (int t = blockIdx.x; t < N1 / 128; t += N1_BLOCKS) {
            const int m0 = t * 128 + wid * 16;
            uint32_t Ah[4][4], Al[4][4];
            load_A(x, m0, gq, tq, Ah, Al);

            #pragma unroll
            for (int half = 0; half < 2; half++) {
                float acc[4][4];
                #pragma unroll
                for (int nt = 0; nt < 4; nt++)
                    #pragma unroll
                    for (int r = 0; r < 4; r++) acc[nt][r] = 0.0f;
                run_chains_half(acc, smem_u, Ah, Al, gq, tq, half * 4);
                epilogue_half(acc, smem_f, outp, m0, gq, tq, half * 4, true);
            }
        }
    } else {
        // ------------------- logit leg -------------------
        if (tid < 64) smem_q[tid] = g_sw34[tid];
        __syncthreads();
        const float bias2 = bs2[0];

        for (int u = blockIdx.x - N1_BLOCKS; u < MPAIR / 256; u += LOGIT_BLOCKS) {
            const int mi = u * 256 + tid;
            const int j  = mi >> 4;
            const int i  = knn[mi];
            float4 pq = g_p1q[i];
            float4 qq = g_p2q[j];
            float prx = pq.x - qq.x, pry = pq.y - qq.y, prz = pq.z - qq.z;

            float acc = 0.0f;
            const float4* pre4 = (const float4*)(g_pre + (size_t)j * 64);
            #pragma unroll
            for (int c4 = 0; c4 < 16; c4++) {
                float4 pv = pre4[c4];
                float4 w0 = smem_q[4*c4+0];
                float4 w1 = smem_q[4*c4+1];
                float4 w2 = smem_q[4*c4+2];
                float4 w3 = smem_q[4*c4+3];
                float h;
                h = fmaf(prx, w0.x, fmaf(pry, w0.y, fmaf(prz, w0.z, pv.x)));
                acc = fmaf(fmaxf(h, 0.f), w0.w, acc);
                h = fmaf(prx, w1.x, fmaf(pry, w1.y, fmaf(prz, w1.z, pv.y)));
                acc = fmaf(fmaxf(h, 0.f), w1.w, acc);
                h = fmaf(prx, w2.x, fmaf(pry, w2.y, fmaf(prz, w2.z, pv.z)));
                acc = fmaf(fmaxf(h, 0.f), w2.w, acc);
                h = fmaf(prx, w3.x, fmaf(pry, w3.y, fmaf(prz, w3.z, pv.w)));
                acc = fmaf(fmaxf(h, 0.f), w3.w, acc);
            }
            float ev = __expf(acc + bias2);
            g_e[mi] = ev;
            atomicAdd(&g_denom[i], ev);
        }
    }
}

// ========= prob-weighted scatter into out: 16 lanes per pair, float4 RED.128 =========
__global__ void __launch_bounds__(256)
scatter_kernel(const int* __restrict__ knn, float* __restrict__ out)
{
    const int tid  = threadIdx.x;
    const int lane = tid & 31, w = tid >> 5;
    const int sub  = lane >> 4;
    const int c4   = lane & 15;

    #pragma unroll
    for (int it = 0; it < 16; it++) {
        const int pidx = w * 32 + it * 2 + sub;
        const int mi = blockIdx.x * 256 + pidx;
        const int j  = mi >> 4;
        const int i  = knn[mi];
        float dn = g_denom[i];
        float prob = g_e[mi] * (dn > 0.f ? 1.0f / dn : 0.0f);
        float4 u = *((const float4*)(g_upfeat + (size_t)j * 64) + c4);
        float4 val = make_float4(u.x * prob, u.y * prob, u.z * prob, u.w * prob);
        atomicAdd((float4*)(out + (size_t)i * 64) + c4, val);
    }
}

extern "C" void kernel_launch(void* const* d_in, const int* in_sizes, int n_in,
                              void* d_out, int out_size)
{
    const float* p1  = (const float*)d_in[0];
    const float* p2  = (const float*)d_in[1];
    const float* x1  = (const float*)d_in[2];
    const float* x2  = (const float*)d_in[3];
    const int*   knn = (const int*)  d_in[4];
    const float* w1  = (const float*)d_in[5];
    const float* b1  = (const float*)d_in[6];
    const float* g1  = (const float*)d_in[7];
    const float* be1 = (const float*)d_in[8];
    const float* m1  = (const float*)d_in[9];
    const float* v1  = (const float*)d_in[10];
    const float* w2  = (const float*)d_in[11];
    const float* b2  = (const float*)d_in[12];
    const float* g2  = (const float*)d_in[13];
    const float* be2 = (const float*)d_in[14];
    const float* m2  = (const float*)d_in[15];
    const float* v2  = (const float*)d_in[16];
    const float* ws1 = (const float*)d_in[17];
    const float* bs1 = (const float*)d_in[18];
    const float* gs  = (const float*)d_in[19];
    const float* bes = (const float*)d_in[20];
    const float* ms  = (const float*)d_in[21];
    const float* vs  = (const float*)d_in[22];
    const float* ws2 = (const float*)d_in[23];
    const float* bs2 = (const float*)d_in[24];
    float* out = (float*)d_out;

    // pack all weights/biases once + init denom + pack p1/p2
    prep_kernel<<<444, 256>>>(w1, b1, g1, be1, m1, v1,
                              w2, b2, g2, be2, m2, v2,
                              ws1, bs1, gs, bes, ms, vs, ws2, p1, p2);
    // upfeat + pre GEMMs (fast fill from prepacked weights)
    gemm_n2_kernel<<<444, 256>>>(x2);
    // y1 -> out  CONCURRENT WITH  logit+exp+denom
    fused_n1_logit_kernel<<<FUSED_BLOCKS, 256>>>(x1, out, knn, bs2);
    // prob-weighted scatter on top of y1
    scatter_kernel<<<MPAIR/256, 256>>>(knn, out);
}

// round 12
// speedup vs baseline: 1.4592x; 1.0313x over previous
#include <cuda_runtime.h>
#include <cuda_bf16.h>
#include <cstdint>

#define N1 262144
#define N2 65536
#define KNN 16
#define MPAIR (N2*KNN)
#define EPSV 1e-5f

#define FUSED_BLOCKS 444
#define N1_BLOCKS 280
#define LOGIT_BLOCKS (FUSED_BLOCKS - N1_BLOCKS)

// ---- static scratch (no runtime allocation allowed) ----
__device__ float    g_upfeat[N2*64];   // relu(bn(x2@w2^T))
__device__ float    g_pre[N2*64];      // x2-part of shrinker linear
__device__ float    g_e[MPAIR];        // exp(logit)
__device__ float    g_denom[N1];       // softmax denominator
__device__ float4   g_p1q[N1];         // packed p1 (xyz_)
__device__ float4   g_p2q[N2];         // packed p2 (xyz_)
__device__ uint32_t g_packW[3*4096];   // prepacked+swizzled bf16 hi/lo weights (w1,w2,ws1)
__device__ float    g_fbW[3*64];       // folded biases
__device__ float4   g_sw34[64];        // shrinker (w3x,w3y,w3z,w2) per channel

// bf16 mma (baseline ISA, sm_80+; lowers to HMMA on sm_103 tensor pipe)
__device__ __forceinline__ void mma16816(float* d, const uint32_t* a, uint32_t b0, uint32_t b1) {
    asm volatile(
        "mma.sync.aligned.m16n8k16.row.col.f32.bf16.bf16.f32 "
        "{%0,%1,%2,%3}, {%4,%5,%6,%7}, {%8,%9}, {%0,%1,%2,%3};"
        : "+f"(d[0]), "+f"(d[1]), "+f"(d[2]), "+f"(d[3])
        : "r"(a[0]), "r"(a[1]), "r"(a[2]), "r"(a[3]), "r"(b0), "r"(b1));
}

__device__ __forceinline__ void split2(float f0, float f1, uint32_t& hi, uint32_t& lo) {
    __nv_bfloat16 h0 = __float2bfloat16_rn(f0);
    __nv_bfloat16 h1 = __float2bfloat16_rn(f1);
    __nv_bfloat162 hp; hp.x = h0; hp.y = h1;
    __nv_bfloat162 lp = __floats2bfloat162_rn(f0 - __bfloat162float(h0),
                                              f1 - __bfloat162float(h1));
    hi = *(uint32_t*)&hp;
    lo = *(uint32_t*)&lp;
}

// ============ prep: pack all weights once + folded biases + sw34 + init ============
__global__ void __launch_bounds__(256)
prep_kernel(const float* __restrict__ w1, const float* __restrict__ b1,
            const float* __restrict__ g1, const float* __restrict__ be1,
            const float* __restrict__ m1, const float* __restrict__ v1,
            const float* __restrict__ w2, const float* __restrict__ b2,
            const float* __restrict__ g2, const float* __restrict__ be2,
            const float* __restrict__ m2, const float* __restrict__ v2,
            const float* __restrict__ ws1, const float* __restrict__ bs1,
            const float* __restrict__ gs, const float* __restrict__ bes,
            const float* __restrict__ ms, const float* __restrict__ vs,
            const float* __restrict__ ws2,
            const float* __restrict__ p1, const float* __restrict__ p2)
{
    const int gid = blockIdx.x * 256 + threadIdx.x;

    if (gid < 3 * 4096) {
        int mat = gid >> 12, idx = gid & 4095;
        const float *w, *gg, *vv; int wstride, wcol0;
        if (mat == 0)      { w = w1;  gg = g1; vv = v1; wstride = 64; wcol0 = 0; }
        else if (mat == 1) { w = w2;  gg = g2; vv = v2; wstride = 64; wcol0 = 0; }
        else               { w = ws1; gg = gs; vv = vs; wstride = 67; wcol0 = 3; }
        int row = idx >> 6, col = idx & 63;
        int r31 = row & 31;
        int ks = r31 >> 3, q = r31 & 7;
        int kk = 16 * ks + ((q < 4) ? 4 * q : 4 * (q - 4) + 2);
        float s  = gg[col] * rsqrtf(vv[col] + EPSV);
        float w0 = w[col * wstride + wcol0 + kk]     * s;
        float wv = w[col * wstride + wcol0 + kk + 1] * s;
        uint32_t hiw, low;
        split2(w0, wv, hiw, low);
        g_packW[mat * 4096 + row * 64 + (col ^ ((row & 3) << 3))] = (row < 32) ? hiw : low;
    } else if (gid < 3 * 4096 + 192) {
        int t = gid - 3 * 4096; int mat = t >> 6, c = t & 63;
        const float *bb, *gg, *be, *mm, *vv;
        if (mat == 0)      { bb = b1;  gg = g1; be = be1; mm = m1; vv = v1; }
        else if (mat == 1) { bb = b2;  gg = g2; be = be2; mm = m2; vv = v2; }
        else               { bb = bs1; gg = gs; be = bes; mm = ms; vv = vs; }
        float s = gg[c] * rsqrtf(vv[c] + EPSV);
        g_fbW[mat * 64 + c] = (bb[c] - mm[c]) * s + be[c];
    } else if (gid < 3 * 4096 + 192 + 64) {
        int c = gid - (3 * 4096 + 192);
        float s = gs[c] * rsqrtf(vs[c] + EPSV);
        g_sw34[c] = make_float4(ws1[c * 67] * s, ws1[c * 67 + 1] * s,
                                ws1[c * 67 + 2] * s, ws2[c]);
    }

    const int tot = gridDim.x * 256;
    for (int i = gid; i < N1; i += tot) {
        g_denom[i] = 0.0f;
        g_p1q[i] = make_float4(p1[3*i], p1[3*i+1], p1[3*i+2], 0.f);
    }
    for (int i = gid; i < N2; i += tot)
        g_p2q[i] = make_float4(p2[3*i], p2[3*i+1], p2[3*i+2], 0.f);
}

// fast smem fill from prepacked global: 16KB coalesced copy + bias
__device__ __forceinline__ void fill_fast(uint32_t* packB, float* fb, int mat, int tid) {
    const float4* src = (const float4*)(g_packW + mat * 4096);
    #pragma unroll
    for (int it = 0; it < 4; it++)
        ((float4*)packB)[it * 256 + tid] = src[it * 256 + tid];
    if (tid < 64) fb[tid] = g_fbW[mat * 64 + tid];
}

__device__ __forceinline__ void load_A(const float* __restrict__ x, int m0, int gq, int tq,
                                       uint32_t Ah[4][4], uint32_t Al[4][4])
{
    const float4* r0 = (const float4*)(x + (size_t)(m0 + gq) * 64);
    const float4* r1 = (const float4*)(x + (size_t)(m0 + gq + 8) * 64);
    #pragma unroll
    for (int ks = 0; ks < 4; ks++) {
        float4 v0 = r0[4 * ks + tq];
        float4 v1 = r1[4 * ks + tq];
        split2(v0.x, v0.y, Ah[ks][0], Al[ks][0]);
        split2(v1.x, v1.y, Ah[ks][1], Al[ks][1]);
        split2(v0.z, v0.w, Ah[ks][2], Al[ks][2]);
        split2(v1.z, v1.w, Ah[ks][3], Al[ks][3]);
    }
}

// 3 accumulating chains over HALF the n-tiles (nt0..nt0+3): acc is 16 regs.
__device__ __forceinline__ void run_chains_half(float acc[4][4], const uint32_t* packB,
                                                const uint32_t Ah[4][4], const uint32_t Al[4][4],
                                                int gq, int tq, int nt0)
{
    const int csw = tq << 3;
    #pragma unroll
    for (int c = 0; c < 3; c++) {
        const uint32_t (*Af)[4] = (c == 2) ? Al : Ah;
        const int rb = (c == 1) ? 32 : 0;
        #pragma unroll
        for (int ks = 0; ks < 4; ks++) {
            const int r0i = (rb + 8 * ks + tq) * 64;
            const int r1i = (rb + 8 * ks + tq + 4) * 64;
            #pragma unroll
            for (int nt = 0; nt < 4; nt++) {
                int coff = (8 * (nt0 + nt) + gq) ^ csw;
                mma16816(acc[nt], Af[ks], packB[r0i + coff], packB[r1i + coff]);
            }
        }
    }
}

__device__ __forceinline__ void epilogue_half(float acc[4][4], const float* fb,
                                              float* __restrict__ o, int m0, int gq, int tq,
                                              int nt0, bool relu)
{
    float* o0 = o + (size_t)(m0 + gq) * 64;
    float* o1 = o + (size_t)(m0 + gq + 8) * 64;
    #pragma unroll
    for (int nt = 0; nt < 4; nt++) {
        int col = 8 * (nt0 + nt) + 2 * tq;
        float2 fbp = *(float2*)&fb[col];
        float2 u, v;
        u.x = acc[nt][0] + fbp.x; u.y = acc[nt][1] + fbp.y;
        v.x = acc[nt][2] + fbp.x; v.y = acc[nt][3] + fbp.y;
        if (relu) {
            u.x = fmaxf(u.x, 0.f); u.y = fmaxf(u.y, 0.f);
            v.x = fmaxf(v.x, 0.f); v.y = fmaxf(v.y, 0.f);
        }
        *(float2*)(o0 + col) = u;
        *(float2*)(o1 + col) = v;
    }
}

// ====== N2 fused GEMM: upfeat (w2, relu) + pre (ws1[:,3:], no relu) ======
__global__ void __launch_bounds__(256, 3)
gemm_n2_kernel(const float* __restrict__ x)
{
    __shared__ uint32_t packB2[64 * 64];
    __shared__ uint32_t packBs[64 * 64];
    __shared__ float fb2[64], fbs[64];
    const int tid = threadIdx.x, wid = tid >> 5, lane = tid & 31;
    const int gq = lane >> 2, tq = lane & 3;

    fill_fast(packB2, fb2, 1, tid);
    fill_fast(packBs, fbs, 2, tid);
    __syncthreads();

    for (int t = blockIdx.x; t < N2 / 128; t += gridDim.x) {
        const int m0 = t * 128 + wid * 16;
        uint32_t Ah[4][4], Al[4][4];
        load_A(x, m0, gq, tq, Ah, Al);

        #pragma unroll
        for (int half = 0; half < 2; half++) {
            float acc[4][4];
            #pragma unroll
            for (int nt = 0; nt < 4; nt++)
                #pragma unroll
                for (int r = 0; r < 4; r++) acc[nt][r] = 0.0f;
            run_chains_half(acc, packB2, Ah, Al, gq, tq, half * 4);
            epilogue_half(acc, fb2, g_upfeat, m0, gq, tq, half * 4, true);

            #pragma unroll
            for (int nt = 0; nt < 4; nt++)
                #pragma unroll
                for (int r = 0; r < 4; r++) acc[nt][r] = 0.0f;
            run_chains_half(acc, packBs, Ah, Al, gq, tq, half * 4);
            epilogue_half(acc, fbs, g_pre, m0, gq, tq, half * 4, false);
        }
    }
}

// ============ FUSED: blocks [0,N1_BLOCKS) do N1 GEMM; rest do logit+exp+denom ============
__global__ void __launch_bounds__(256, 3)
fused_n1_logit_kernel(const float* __restrict__ x,
                      float* __restrict__ outp,
                      const int*   __restrict__ knn,
                      const float* __restrict__ bs2)
{
    __shared__ uint32_t smem_u[64 * 64];     // n1: packB
    __shared__ float4   smem_q[64];          // logit: sw34
    __shared__ float    smem_f[64];          // n1: fb
    const int tid = threadIdx.x;

    if (blockIdx.x < N1_BLOCKS) {
        // ------------------- N1 GEMM leg: out = relu(bn(x1@w1^T)) -------------------
        const int wid = tid >> 5, lane = tid & 31;
        const int gq = lane >> 2, tq = lane & 3;

        fill_fast(smem_u, smem_f, 0, tid);
        __syncthreads();

        for (int t = blockIdx.x; t < N1 / 128; t += N1_BLOCKS) {
            const int m0 = t * 128 + wid * 16;
            uint32_t Ah[4][4], Al[4][4];
            load_A(x, m0, gq, tq, Ah, Al);

            #pragma unroll
            for (int half = 0; half < 2; half++) {
                float acc[4][4];
                #pragma unroll
                for (int nt = 0; nt < 4; nt++)
                    #pragma unroll
                    for (int r = 0; r < 4; r++) acc[nt][r] = 0.0f;
                run_chains_half(acc, smem_u, Ah, Al, gq, tq, half * 4);
                epilogue_half(acc, smem_f, outp, m0, gq, tq, half * 4, true);
            }
        }
    } else {
        // ------------------- logit leg -------------------
        if (tid < 64) smem_q[tid] = g_sw34[tid];
        __syncthreads();
        const float bias2 = bs2[0];

        for (int u = blockIdx.x - N1_BLOCKS; u < MPAIR / 256; u += LOGIT_BLOCKS) {
            const int mi = u * 256 + tid;
            const int j  = mi >> 4;
            const int i  = knn[mi];
            float4 pq = g_p1q[i];
            float4 qq = g_p2q[j];
            float prx = pq.x - qq.x, pry = pq.y - qq.y, prz = pq.z - qq.z;

            float acc = 0.0f;
            const float4* pre4 = (const float4*)(g_pre + (size_t)j * 64);
            #pragma unroll
            for (int c4 = 0; c4 < 16; c4++) {
                float4 pv = pre4[c4];
                float4 w0 = smem_q[4*c4+0];
                float4 w1 = smem_q[4*c4+1];
                float4 w2 = smem_q[4*c4+2];
                float4 w3 = smem_q[4*c4+3];
                float h;
                h = fmaf(prx, w0.x, fmaf(pry, w0.y, fmaf(prz, w0.z, pv.x)));
                acc = fmaf(fmaxf(h, 0.f), w0.w, acc);
                h = fmaf(prx, w1.x, fmaf(pry, w1.y, fmaf(prz, w1.z, pv.y)));
                acc = fmaf(fmaxf(h, 0.f), w1.w, acc);
                h = fmaf(prx, w2.x, fmaf(pry, w2.y, fmaf(prz, w2.z, pv.z)));
                acc = fmaf(fmaxf(h, 0.f), w2.w, acc);
                h = fmaf(prx, w3.x, fmaf(pry, w3.y, fmaf(prz, w3.z, pv.w)));
                acc = fmaf(fmaxf(h, 0.f), w3.w, acc);
            }
            float ev = __expf(acc + bias2);
            g_e[mi] = ev;
            atomicAdd(&g_denom[i], ev);
        }
    }
}

// ========= prob-weighted scatter v2: 16-lane group OWNS one coarse point j =========
// upfeat[j] row loaded ONCE per group (float4/lane) and reused for all 16 pairs.
// Lane k loads pair k's (i, e, denom) coalesced; shfl broadcasts (i_k, prob_k);
// every lane issues 16 float4 RED.128 reusing its register-resident u.
__global__ void __launch_bounds__(256)
scatter_kernel(const int* __restrict__ knn, float* __restrict__ out)
{
    const int tid  = threadIdx.x;
    const int lane = tid & 31, w = tid >> 5;
    const int half = lane >> 4;          // which coarse point of this warp's two
    const int c4   = lane & 15;          // float4 channel group / pair slot

    const int j  = blockIdx.x * 16 + w * 2 + half;      // coarse point
    const int mi = j * 16 + c4;                          // this lane's pair

    // pair-local values (coalesced loads)
    const int   i_l = knn[mi];
    const float ev  = g_e[mi];
    const float dn  = g_denom[i_l];
    const float prob_l = ev * (dn > 0.f ? 1.0f / dn : 0.0f);

    // upfeat row: one float4 per lane, loaded once
    const float4 u = *((const float4*)(g_upfeat + (size_t)j * 64) + c4);

    const int base = half << 4;
    #pragma unroll
    for (int k = 0; k < 16; k++) {
        float prob_b = __shfl_sync(0xffffffffu, prob_l, base + k);
        int   i_b    = __shfl_sync(0xffffffffu, i_l,    base + k);
        float4 val = make_float4(u.x * prob_b, u.y * prob_b, u.z * prob_b, u.w * prob_b);
        atomicAdd((float4*)(out + (size_t)i_b * 64) + c4, val);
    }
}

extern "C" void kernel_launch(void* const* d_in, const int* in_sizes, int n_in,
                              void* d_out, int out_size)
{
    const float* p1  = (const float*)d_in[0];
    const float* p2  = (const float*)d_in[1];
    const float* x1  = (const float*)d_in[2];
    const float* x2  = (const float*)d_in[3];
    const int*   knn = (const int*)  d_in[4];
    const float* w1  = (const float*)d_in[5];
    const float* b1  = (const float*)d_in[6];
    const float* g1  = (const float*)d_in[7];
    const float* be1 = (const float*)d_in[8];
    const float* m1  = (const float*)d_in[9];
    const float* v1  = (const float*)d_in[10];
    const float* w2  = (const float*)d_in[11];
    const float* b2  = (const float*)d_in[12];
    const float* g2  = (const float*)d_in[13];
    const float* be2 = (const float*)d_in[14];
    const float* m2  = (const float*)d_in[15];
    const float* v2  = (const float*)d_in[16];
    const float* ws1 = (const float*)d_in[17];
    const float* bs1 = (const float*)d_in[18];
    const float* gs  = (const float*)d_in[19];
    const float* bes = (const float*)d_in[20];
    const float* ms  = (const float*)d_in[21];
    const float* vs  = (const float*)d_in[22];
    const float* ws2 = (const float*)d_in[23];
    const float* bs2 = (const float*)d_in[24];
    float* out = (float*)d_out;

    // pack all weights/biases once + init denom + pack p1/p2
    prep_kernel<<<444, 256>>>(w1, b1, g1, be1, m1, v1,
                              w2, b2, g2, be2, m2, v2,
                              ws1, bs1, gs, bes, ms, vs, ws2, p1, p2);
    // upfeat + pre GEMMs (fast fill from prepacked weights)
    gemm_n2_kernel<<<444, 256>>>(x2);
    // y1 -> out  CONCURRENT WITH  logit+exp+denom
    fused_n1_logit_kernel<<<FUSED_BLOCKS, 256>>>(x1, out, knn, bs2);
    // prob-weighted scatter on top of y1 (j-owned groups, u loaded once)
    scatter_kernel<<<N2/16, 256>>>(knn, out);
}

// round 13
// speedup vs baseline: 1.5790x; 1.0821x over previous
#include <cuda_runtime.h>
#include <cuda_bf16.h>
#include <cstdint>

#define N1 262144
#define N2 65536
#define KNN 16
#define MPAIR (N2*KNN)
#define EPSV 1e-5f

#define N1_JOBS (N1/128)          // 2048
#define N2_JOBS (N2/128)          // 512
#define ALL_JOBS (N1_JOBS + N2_JOBS)

// ---- static scratch (no runtime allocation allowed) ----
__device__ float    g_upfeat[N2*64];   // relu(bn(x2@w2^T))
__device__ float    g_pre[N2*64];      // x2-part of shrinker linear
__device__ float    g_e[MPAIR];        // exp(logit)
__device__ float    g_denom[N1];       // softmax denominator
__device__ float4   g_p1q[N1];         // packed p1 (xyz_)
__device__ float4   g_p2q[N2];         // packed p2 (xyz_)
__device__ uint32_t g_packW[3*4096];   // prepacked+swizzled bf16 hi/lo weights (w1,w2,ws1)
__device__ float    g_fbW[3*64];       // folded biases
__device__ float4   g_sw34[64];        // shrinker (w3x,w3y,w3z,w2) per channel

// bf16 mma (baseline ISA, sm_80+; lowers to HMMA on sm_103 tensor pipe)
__device__ __forceinline__ void mma16816(float* d, const uint32_t* a, uint32_t b0, uint32_t b1) {
    asm volatile(
        "mma.sync.aligned.m16n8k16.row.col.f32.bf16.bf16.f32 "
        "{%0,%1,%2,%3}, {%4,%5,%6,%7}, {%8,%9}, {%0,%1,%2,%3};"
        : "+f"(d[0]), "+f"(d[1]), "+f"(d[2]), "+f"(d[3])
        : "r"(a[0]), "r"(a[1]), "r"(a[2]), "r"(a[3]), "r"(b0), "r"(b1));
}

// split (f0,f1) -> packed bf16 hi-pair + lo-pair (residual). Bit-trick version:
// hi floats recovered from the packed pair by shift/mask (bf16 == top bits of f32).
__device__ __forceinline__ void split2(float f0, float f1, uint32_t& hi, uint32_t& lo) {
    uint32_t hp;
    asm("cvt.rn.bf16x2.f32 %0, %1, %2;" : "=r"(hp) : "f"(f1), "f"(f0));
    float h0 = __uint_as_float(hp << 16);
    float h1 = __uint_as_float(hp & 0xFFFF0000u);
    float l0 = f0 - h0, l1 = f1 - h1;
    uint32_t lp;
    asm("cvt.rn.bf16x2.f32 %0, %1, %2;" : "=r"(lp) : "f"(l1), "f"(l0));
    hi = hp; lo = lp;
}

// ============ prep: pack all weights once + folded biases + sw34 + init ============
__global__ void __launch_bounds__(256)
prep_kernel(const float* __restrict__ w1, const float* __restrict__ b1,
            const float* __restrict__ g1, const float* __restrict__ be1,
            const float* __restrict__ m1, const float* __restrict__ v1,
            const float* __restrict__ w2, const float* __restrict__ b2,
            const float* __restrict__ g2, const float* __restrict__ be2,
            const float* __restrict__ m2, const float* __restrict__ v2,
            const float* __restrict__ ws1, const float* __restrict__ bs1,
            const float* __restrict__ gs, const float* __restrict__ bes,
            const float* __restrict__ ms, const float* __restrict__ vs,
            const float* __restrict__ ws2,
            const float* __restrict__ p1, const float* __restrict__ p2)
{
    const int gid = blockIdx.x * 256 + threadIdx.x;

    if (gid < 3 * 4096) {
        int mat = gid >> 12, idx = gid & 4095;
        const float *w, *gg, *vv; int wstride, wcol0;
        if (mat == 0)      { w = w1;  gg = g1; vv = v1; wstride = 64; wcol0 = 0; }
        else if (mat == 1) { w = w2;  gg = g2; vv = v2; wstride = 64; wcol0 = 0; }
        else               { w = ws1; gg = gs; vv = vs; wstride = 67; wcol0 = 3; }
        int row = idx >> 6, col = idx & 63;
        int r31 = row & 31;
        int ks = r31 >> 3, q = r31 & 7;
        int kk = 16 * ks + ((q < 4) ? 4 * q : 4 * (q - 4) + 2);
        float s  = gg[col] * rsqrtf(vv[col] + EPSV);
        float w0 = w[col * wstride + wcol0 + kk]     * s;
        float wv = w[col * wstride + wcol0 + kk + 1] * s;
        uint32_t hiw, low;
        split2(w0, wv, hiw, low);
        g_packW[mat * 4096 + row * 64 + (col ^ ((row & 3) << 3))] = (row < 32) ? hiw : low;
    } else if (gid < 3 * 4096 + 192) {
        int t = gid - 3 * 4096; int mat = t >> 6, c = t & 63;
        const float *bb, *gg, *be, *mm, *vv;
        if (mat == 0)      { bb = b1;  gg = g1; be = be1; mm = m1; vv = v1; }
        else if (mat == 1) { bb = b2;  gg = g2; be = be2; mm = m2; vv = v2; }
        else               { bb = bs1; gg = gs; be = bes; mm = ms; vv = vs; }
        float s = gg[c] * rsqrtf(vv[c] + EPSV);
        g_fbW[mat * 64 + c] = (bb[c] - mm[c]) * s + be[c];
    } else if (gid < 3 * 4096 + 192 + 64) {
        int c = gid - (3 * 4096 + 192);
        float s = gs[c] * rsqrtf(vs[c] + EPSV);
        g_sw34[c] = make_float4(ws1[c * 67] * s, ws1[c * 67 + 1] * s,
                                ws1[c * 67 + 2] * s, ws2[c]);
    }

    const int tot = gridDim.x * 256;
    for (int i = gid; i < N1; i += tot) {
        g_denom[i] = 0.0f;
        g_p1q[i] = make_float4(p1[3*i], p1[3*i+1], p1[3*i+2], 0.f);
    }
    for (int i = gid; i < N2; i += tot)
        g_p2q[i] = make_float4(p2[3*i], p2[3*i+1], p2[3*i+2], 0.f);
}

__device__ __forceinline__ void load_A(const float* __restrict__ x, int m0, int gq, int tq,
                                       uint32_t Ah[4][4], uint32_t Al[4][4])
{
    const float4* r0 = (const float4*)(x + (size_t)(m0 + gq) * 64);
    const float4* r1 = (const float4*)(x + (size_t)(m0 + gq + 8) * 64);
    #pragma unroll
    for (int ks = 0; ks < 4; ks++) {
        float4 v0 = r0[4 * ks + tq];
        float4 v1 = r1[4 * ks + tq];
        split2(v0.x, v0.y, Ah[ks][0], Al[ks][0]);
        split2(v1.x, v1.y, Ah[ks][1], Al[ks][1]);
        split2(v0.z, v0.w, Ah[ks][2], Al[ks][2]);
        split2(v1.z, v1.w, Ah[ks][3], Al[ks][3]);
    }
}

// 3 accumulating chains over HALF the n-tiles (nt0..nt0+3): acc is 16 regs.
__device__ __forceinline__ void run_chains_half(float acc[4][4], const uint32_t* packB,
                                                const uint32_t Ah[4][4], const uint32_t Al[4][4],
                                                int gq, int tq, int nt0)
{
    const int csw = tq << 3;
    #pragma unroll
    for (int c = 0; c < 3; c++) {
        const uint32_t (*Af)[4] = (c == 2) ? Al : Ah;
        const int rb = (c == 1) ? 32 : 0;
        #pragma unroll
        for (int ks = 0; ks < 4; ks++) {
            const int r0i = (rb + 8 * ks + tq) * 64;
            const int r1i = (rb + 8 * ks + tq + 4) * 64;
            #pragma unroll
            for (int nt = 0; nt < 4; nt++) {
                int coff = (8 * (nt0 + nt) + gq) ^ csw;
                mma16816(acc[nt], Af[ks], packB[r0i + coff], packB[r1i + coff]);
            }
        }
    }
}

// epilogue: folded bias read from GLOBAL (L1-cached, tiny) to keep smem <= 48 KB
__device__ __forceinline__ void epilogue_half(float acc[4][4], const float* __restrict__ fb,
                                              float* __restrict__ o, int m0, int gq, int tq,
                                              int nt0, bool relu)
{
    float* o0 = o + (size_t)(m0 + gq) * 64;
    float* o1 = o + (size_t)(m0 + gq + 8) * 64;
    #pragma unroll
    for (int nt = 0; nt < 4; nt++) {
        int col = 8 * (nt0 + nt) + 2 * tq;
        float2 fbp = *(const float2*)(fb + col);
        float2 u, v;
        u.x = acc[nt][0] + fbp.x; u.y = acc[nt][1] + fbp.y;
        v.x = acc[nt][2] + fbp.x; v.y = acc[nt][3] + fbp.y;
        if (relu) {
            u.x = fmaxf(u.x, 0.f); u.y = fmaxf(u.y, 0.f);
            v.x = fmaxf(v.x, 0.f); v.y = fmaxf(v.y, 0.f);
        }
        *(float2*)(o0 + col) = u;
        *(float2*)(o1 + col) = v;
    }
}

// ====== ALL GEMM tiles in one packed kernel: 2048 n1 jobs + 512 n2 double-jobs ======
__global__ void __launch_bounds__(256, 3)
gemm_all_kernel(const float* __restrict__ x1, const float* __restrict__ x2,
                float* __restrict__ outp)
{
    __shared__ uint32_t packW[3 * 4096];   // exactly 48 KB
    const int tid = threadIdx.x, wid = tid >> 5, lane = tid & 31;
    const int gq = lane >> 2, tq = lane & 3;

    // fill all three weight mats: 12 coalesced float4 per thread
    {
        const float4* src = (const float4*)g_packW;
        #pragma unroll
        for (int it = 0; it < 12; it++)
            ((float4*)packW)[it * 256 + tid] = src[it * 256 + tid];
    }
    __syncthreads();

    for (int job = blockIdx.x; job < ALL_JOBS; job += gridDim.x) {
        if (job < N1_JOBS) {
            // ---- n1 tile: out = relu(bn(x1@w1^T)) ----
            const int m0 = job * 128 + wid * 16;
            uint32_t Ah[4][4], Al[4][4];
            load_A(x1, m0, gq, tq, Ah, Al);
            #pragma unroll
            for (int half = 0; half < 2; half++) {
                float acc[4][4];
                #pragma unroll
                for (int nt = 0; nt < 4; nt++)
                    #pragma unroll
                    for (int r = 0; r < 4; r++) acc[nt][r] = 0.0f;
                run_chains_half(acc, packW, Ah, Al, gq, tq, half * 4);
                epilogue_half(acc, g_fbW, outp, m0, gq, tq, half * 4, true);
            }
        } else {
            // ---- n2 tile: upfeat (w2, relu) + pre (ws1, no relu) ----
            const int m0 = (job - N1_JOBS) * 128 + wid * 16;
            uint32_t Ah[4][4], Al[4][4];
            load_A(x2, m0, gq, tq, Ah, Al);
            #pragma unroll
            for (int half = 0; half < 2; half++) {
                float acc[4][4];
                #pragma unroll
                for (int nt = 0; nt < 4; nt++)
                    #pragma unroll
                    for (int r = 0; r < 4; r++) acc[nt][r] = 0.0f;
                run_chains_half(acc, packW + 4096, Ah, Al, gq, tq, half * 4);
                epilogue_half(acc, g_fbW + 64, g_upfeat, m0, gq, tq, half * 4, true);

                #pragma unroll
                for (int nt = 0; nt < 4; nt++)
                    #pragma unroll
                    for (int r = 0; r < 4; r++) acc[nt][r] = 0.0f;
                run_chains_half(acc, packW + 8192, Ah, Al, gq, tq, half * 4);
                epilogue_half(acc, g_fbW + 128, g_pre, m0, gq, tq, half * 4, false);
            }
        }
    }
}

// ===================== logit + exp + denom (thread per pair, float4 weights) =====================
__global__ void __launch_bounds__(256)
logit_kernel(const int* __restrict__ knn, const float* __restrict__ bs2)
{
    __shared__ float4 smem_q[64];
    const int tid = threadIdx.x;
    if (tid < 64) smem_q[tid] = g_sw34[tid];
    __syncthreads();
    const float bias2 = bs2[0];

    const int mi = blockIdx.x * 256 + tid;
    const int j  = mi >> 4;
    const int i  = knn[mi];
    float4 pq = g_p1q[i];
    float4 qq = g_p2q[j];
    float prx = pq.x - qq.x, pry = pq.y - qq.y, prz = pq.z - qq.z;

    float acc = 0.0f;
    const float4* pre4 = (const float4*)(g_pre + (size_t)j * 64);
    #pragma unroll
    for (int c4 = 0; c4 < 16; c4++) {
        float4 pv = pre4[c4];
        float4 w0 = smem_q[4*c4+0];
        float4 w1 = smem_q[4*c4+1];
        float4 w2 = smem_q[4*c4+2];
        float4 w3 = smem_q[4*c4+3];
        float h;
        h = fmaf(prx, w0.x, fmaf(pry, w0.y, fmaf(prz, w0.z, pv.x)));
        acc = fmaf(fmaxf(h, 0.f), w0.w, acc);
        h = fmaf(prx, w1.x, fmaf(pry, w1.y, fmaf(prz, w1.z, pv.y)));
        acc = fmaf(fmaxf(h, 0.f), w1.w, acc);
        h = fmaf(prx, w2.x, fmaf(pry, w2.y, fmaf(prz, w2.z, pv.z)));
        acc = fmaf(fmaxf(h, 0.f), w2.w, acc);
        h = fmaf(prx, w3.x, fmaf(pry, w3.y, fmaf(prz, w3.z, pv.w)));
        acc = fmaf(fmaxf(h, 0.f), w3.w, acc);
    }
    float ev = __expf(acc + bias2);
    g_e[mi] = ev;
    atomicAdd(&g_denom[i], ev);
}

// ========= prob-weighted scatter: 16-lane group owns one coarse point j =========
__global__ void __launch_bounds__(256)
scatter_kernel(const int* __restrict__ knn, float* __restrict__ out)
{
    const int tid  = threadIdx.x;
    const int lane = tid & 31, w = tid >> 5;
    const int half = lane >> 4;
    const int c4   = lane & 15;

    const int j  = blockIdx.x * 16 + w * 2 + half;
    const int mi = j * 16 + c4;

    const int   i_l = knn[mi];
    const float ev  = g_e[mi];
    const float dn  = g_denom[i_l];
    const float prob_l = ev * (dn > 0.f ? 1.0f / dn : 0.0f);

    const float4 u = *((const float4*)(g_upfeat + (size_t)j * 64) + c4);

    const int base = half << 4;
    #pragma unroll
    for (int k = 0; k < 16; k++) {
        float prob_b = __shfl_sync(0xffffffffu, prob_l, base + k);
        int   i_b    = __shfl_sync(0xffffffffu, i_l,    base + k);
        float4 val = make_float4(u.x * prob_b, u.y * prob_b, u.z * prob_b, u.w * prob_b);
        atomicAdd((float4*)(out + (size_t)i_b * 64) + c4, val);
    }
}

extern "C" void kernel_launch(void* const* d_in, const int* in_sizes, int n_in,
                              void* d_out, int out_size)
{
    const float* p1  = (const float*)d_in[0];
    const float* p2  = (const float*)d_in[1];
    const float* x1  = (const float*)d_in[2];
    const float* x2  = (const float*)d_in[3];
    const int*   knn = (const int*)  d_in[4];
    const float* w1  = (const float*)d_in[5];
    const float* b1  = (const float*)d_in[6];
    const float* g1  = (const float*)d_in[7];
    const float* be1 = (const float*)d_in[8];
    const float* m1  = (const float*)d_in[9];
    const float* v1  = (const float*)d_in[10];
    const float* w2  = (const float*)d_in[11];
    const float* b2  = (const float*)d_in[12];
    const float* g2  = (const float*)d_in[13];
    const float* be2 = (const float*)d_in[14];
    const float* m2  = (const float*)d_in[15];
    const float* v2  = (const float*)d_in[16];
    const float* ws1 = (const float*)d_in[17];
    const float* bs1 = (const float*)d_in[18];
    const float* gs  = (const float*)d_in[19];
    const float* bes = (const float*)d_in[20];
    const float* ms  = (const float*)d_in[21];
    const float* vs  = (const float*)d_in[22];
    const float* ws2 = (const float*)d_in[23];
    const float* bs2 = (const float*)d_in[24];
    float* out = (float*)d_out;

    // pack all weights/biases once + init denom + pack p1/p2
    prep_kernel<<<444, 256>>>(w1, b1, g1, be1, m1, v1,
                              w2, b2, g2, be2, m2, v2,
                              ws1, bs1, gs, bes, ms, vs, ws2, p1, p2);
    // ALL GEMM tiles (n1 -> out, n2 -> upfeat+pre) in one packed kernel
    gemm_all_kernel<<<444, 256>>>(x1, x2, out);
    // logit + exp + denom
    logit_kernel<<<MPAIR/256, 256>>>(knn, bs2);
    // prob-weighted scatter on top of y1
    scatter_kernel<<<N2/16, 256>>>(knn, out);
}

// round 14
// speedup vs baseline: 1.6835x; 1.0662x over previous
#include <cuda_runtime.h>
#include <cuda_bf16.h>
#include <cstdint>

#define N1 262144
#define N2 65536
#define KNN 16
#define MPAIR (N2*KNN)
#define EPSV 1e-5f

#define N2_JOBS2 (N2/256)          // 256  (each: upfeat+pre, 256 rows)
#define N1_JOBS2 (N1/256)          // 1024 (each: 256 rows)
#define ALL_JOBS (N1_JOBS2 + N2_JOBS2)

// ---- static scratch (no runtime allocation allowed) ----
__device__ float    g_upfeat[N2*64];   // relu(bn(x2@w2^T))
__device__ float    g_pre[N2*64];      // x2-part of shrinker linear
__device__ float    g_e[MPAIR];        // exp(logit)
__device__ float    g_denom[N1];       // softmax denominator
__device__ float4   g_p1q[N1];         // packed p1 (xyz_)
__device__ float4   g_p2q[N2];         // packed p2 (xyz_)
__device__ uint32_t g_packW[3*4096];   // prepacked+swizzled bf16 hi/lo weights (w1,w2,ws1)
__device__ float    g_fbW[3*64];       // folded biases
__device__ float4   g_sw34[64];        // shrinker (w3x,w3y,w3z,w2) per channel

// bf16 mma (baseline ISA, sm_80+; lowers to HMMA on sm_103 tensor pipe)
__device__ __forceinline__ void mma16816(float* d, const uint32_t* a, uint32_t b0, uint32_t b1) {
    asm volatile(
        "mma.sync.aligned.m16n8k16.row.col.f32.bf16.bf16.f32 "
        "{%0,%1,%2,%3}, {%4,%5,%6,%7}, {%8,%9}, {%0,%1,%2,%3};"
        : "+f"(d[0]), "+f"(d[1]), "+f"(d[2]), "+f"(d[3])
        : "r"(a[0]), "r"(a[1]), "r"(a[2]), "r"(a[3]), "r"(b0), "r"(b1));
}

// split (f0,f1) -> packed bf16 hi-pair + lo-pair (residual). Bit-trick version.
__device__ __forceinline__ void split2(float f0, float f1, uint32_t& hi, uint32_t& lo) {
    uint32_t hp;
    asm("cvt.rn.bf16x2.f32 %0, %1, %2;" : "=r"(hp) : "f"(f1), "f"(f0));
    float h0 = __uint_as_float(hp << 16);
    float h1 = __uint_as_float(hp & 0xFFFF0000u);
    float l0 = f0 - h0, l1 = f1 - h1;
    uint32_t lp;
    asm("cvt.rn.bf16x2.f32 %0, %1, %2;" : "=r"(lp) : "f"(l1), "f"(l0));
    hi = hp; lo = lp;
}

// ============ prep: pack all weights once + folded biases + sw34 + init ============
__global__ void __launch_bounds__(256)
prep_kernel(const float* __restrict__ w1, const float* __restrict__ b1,
            const float* __restrict__ g1, const float* __restrict__ be1,
            const float* __restrict__ m1, const float* __restrict__ v1,
            const float* __restrict__ w2, const float* __restrict__ b2,
            const float* __restrict__ g2, const float* __restrict__ be2,
            const float* __restrict__ m2, const float* __restrict__ v2,
            const float* __restrict__ ws1, const float* __restrict__ bs1,
            const float* __restrict__ gs, const float* __restrict__ bes,
            const float* __restrict__ ms, const float* __restrict__ vs,
            const float* __restrict__ ws2,
            const float* __restrict__ p1, const float* __restrict__ p2)
{
    const int gid = blockIdx.x * 256 + threadIdx.x;

    if (gid < 3 * 4096) {
        int mat = gid >> 12, idx = gid & 4095;
        const float *w, *gg, *vv; int wstride, wcol0;
        if (mat == 0)      { w = w1;  gg = g1; vv = v1; wstride = 64; wcol0 = 0; }
        else if (mat == 1) { w = w2;  gg = g2; vv = v2; wstride = 64; wcol0 = 0; }
        else               { w = ws1; gg = gs; vv = vs; wstride = 67; wcol0 = 3; }
        int row = idx >> 6, col = idx & 63;
        int r31 = row & 31;
        int ks = r31 >> 3, q = r31 & 7;
        int kk = 16 * ks + ((q < 4) ? 4 * q : 4 * (q - 4) + 2);
        float s  = gg[col] * rsqrtf(vv[col] + EPSV);
        float w0 = w[col * wstride + wcol0 + kk]     * s;
        float wv = w[col * wstride + wcol0 + kk + 1] * s;
        uint32_t hiw, low;
        split2(w0, wv, hiw, low);
        g_packW[mat * 4096 + row * 64 + (col ^ ((row & 3) << 3))] = (row < 32) ? hiw : low;
    } else if (gid < 3 * 4096 + 192) {
        int t = gid - 3 * 4096; int mat = t >> 6, c = t & 63;
        const float *bb, *gg, *be, *mm, *vv;
        if (mat == 0)      { bb = b1;  gg = g1; be = be1; mm = m1; vv = v1; }
        else if (mat == 1) { bb = b2;  gg = g2; be = be2; mm = m2; vv = v2; }
        else               { bb = bs1; gg = gs; be = bes; mm = ms; vv = vs; }
        float s = gg[c] * rsqrtf(vv[c] + EPSV);
        g_fbW[mat * 64 + c] = (bb[c] - mm[c]) * s + be[c];
    } else if (gid < 3 * 4096 + 192 + 64) {
        int c = gid - (3 * 4096 + 192);
        float s = gs[c] * rsqrtf(vs[c] + EPSV);
        g_sw34[c] = make_float4(ws1[c * 67] * s, ws1[c * 67 + 1] * s,
                                ws1[c * 67 + 2] * s, ws2[c]);
    }

    const int tot = gridDim.x * 256;
    for (int i = gid; i < N1; i += tot) {
        g_denom[i] = 0.0f;
        g_p1q[i] = make_float4(p1[3*i], p1[3*i+1], p1[3*i+2], 0.f);
    }
    for (int i = gid; i < N2; i += tot)
        g_p2q[i] = make_float4(p2[3*i], p2[3*i+1], p2[3*i+2], 0.f);
}

__device__ __forceinline__ void load_A(const float* __restrict__ x, int m0, int gq, int tq,
                                       uint32_t Ah[4][4], uint32_t Al[4][4])
{
    const float4* r0 = (const float4*)(x + (size_t)(m0 + gq) * 64);
    const float4* r1 = (const float4*)(x + (size_t)(m0 + gq + 8) * 64);
    #pragma unroll
    for (int ks = 0; ks < 4; ks++) {
        float4 v0 = r0[4 * ks + tq];
        float4 v1 = r1[4 * ks + tq];
        split2(v0.x, v0.y, Ah[ks][0], Al[ks][0]);
        split2(v1.x, v1.y, Ah[ks][1], Al[ks][1]);
        split2(v0.z, v0.w, Ah[ks][2], Al[ks][2]);
        split2(v1.z, v1.w, Ah[ks][3], Al[ks][3]);
    }
}

// DUAL-A 3-chain MMA over half the n-tiles. Per (ks,nt): 4 LDS serve 6 MMAs
// (Bh shared between the Ah and Al chains; both A tiles share all B words).
__device__ __forceinline__ void run_chains_dual(float acc0[4][4], float acc1[4][4],
                                                const uint32_t* packB,
                                                const uint32_t Ah0[4][4], const uint32_t Al0[4][4],
                                                const uint32_t Ah1[4][4], const uint32_t Al1[4][4],
                                                int gq, int tq, int nt0)
{
    const int csw = tq << 3;
    #pragma unroll
    for (int ks = 0; ks < 4; ks++) {
        const int rh0 = (8 * ks + tq) * 64;
        const int rh1 = (8 * ks + tq + 4) * 64;
        const int rl0 = (32 + 8 * ks + tq) * 64;
        const int rl1 = (32 + 8 * ks + tq + 4) * 64;
        #pragma unroll
        for (int nt = 0; nt < 4; nt++) {
            const int coff = (8 * (nt0 + nt) + gq) ^ csw;
            uint32_t bh0 = packB[rh0 + coff], bh1 = packB[rh1 + coff];
            uint32_t bl0 = packB[rl0 + coff], bl1 = packB[rl1 + coff];
            mma16816(acc0[nt], Ah0[ks], bh0, bh1);
            mma16816(acc1[nt], Ah1[ks], bh0, bh1);
            mma16816(acc0[nt], Ah0[ks], bl0, bl1);
            mma16816(acc1[nt], Ah1[ks], bl0, bl1);
            mma16816(acc0[nt], Al0[ks], bh0, bh1);
            mma16816(acc1[nt], Al1[ks], bh0, bh1);
        }
    }
}

// epilogue: folded bias read from GLOBAL (L1-cached, tiny)
__device__ __forceinline__ void epilogue_half(float acc[4][4], const float* __restrict__ fb,
                                              float* __restrict__ o, int m0, int gq, int tq,
                                              int nt0, bool relu)
{
    float* o0 = o + (size_t)(m0 + gq) * 64;
    float* o1 = o + (size_t)(m0 + gq + 8) * 64;
    #pragma unroll
    for (int nt = 0; nt < 4; nt++) {
        int col = 8 * (nt0 + nt) + 2 * tq;
        float2 fbp = *(const float2*)(fb + col);
        float2 u, v;
        u.x = acc[nt][0] + fbp.x; u.y = acc[nt][1] + fbp.y;
        v.x = acc[nt][2] + fbp.x; v.y = acc[nt][3] + fbp.y;
        if (relu) {
            u.x = fmaxf(u.x, 0.f); u.y = fmaxf(u.y, 0.f);
            v.x = fmaxf(v.x, 0.f); v.y = fmaxf(v.y, 0.f);
        }
        *(float2*)(o0 + col) = u;
        *(float2*)(o1 + col) = v;
    }
}

// ====== ALL GEMM tiles, 256-row dual-A jobs: 256 n2 jobs (first) + 1024 n1 jobs ======
__global__ void __launch_bounds__(256, 2)
gemm_all_kernel(const float* __restrict__ x1, const float* __restrict__ x2,
                float* __restrict__ outp)
{
    __shared__ uint32_t packW[3 * 4096];   // 48 KB
    const int tid = threadIdx.x, wid = tid >> 5, lane = tid & 31;
    const int gq = lane >> 2, tq = lane & 3;

    {
        const float4* src = (const float4*)g_packW;
        #pragma unroll
        for (int it = 0; it < 12; it++)
            ((float4*)packW)[it * 256 + tid] = src[it * 256 + tid];
    }
    __syncthreads();

    for (int job = blockIdx.x; job < ALL_JOBS; job += gridDim.x) {
        if (job < N2_JOBS2) {
            // ---- n2 dual tile: upfeat (w2, relu) + pre (ws1, no relu) ----
            const int m0 = job * 256 + wid * 16;
            const int m1 = m0 + 128;
            uint32_t Ah0[4][4], Al0[4][4], Ah1[4][4], Al1[4][4];
            load_A(x2, m0, gq, tq, Ah0, Al0);
            load_A(x2, m1, gq, tq, Ah1, Al1);
            #pragma unroll
            for (int half = 0; half < 2; half++) {
                float acc0[4][4], acc1[4][4];
                #pragma unroll
                for (int nt = 0; nt < 4; nt++)
                    #pragma unroll
                    for (int r = 0; r < 4; r++) { acc0[nt][r] = 0.f; acc1[nt][r] = 0.f; }
                run_chains_dual(acc0, acc1, packW + 4096, Ah0, Al0, Ah1, Al1, gq, tq, half * 4);
                epilogue_half(acc0, g_fbW + 64, g_upfeat, m0, gq, tq, half * 4, true);
                epilogue_half(acc1, g_fbW + 64, g_upfeat, m1, gq, tq, half * 4, true);

                #pragma unroll
                for (int nt = 0; nt < 4; nt++)
                    #pragma unroll
                    for (int r = 0; r < 4; r++) { acc0[nt][r] = 0.f; acc1[nt][r] = 0.f; }
                run_chains_dual(acc0, acc1, packW + 8192, Ah0, Al0, Ah1, Al1, gq, tq, half * 4);
                epilogue_half(acc0, g_fbW + 128, g_pre, m0, gq, tq, half * 4, false);
                epilogue_half(acc1, g_fbW + 128, g_pre, m1, gq, tq, half * 4, false);
            }
        } else {
            // ---- n1 dual tile: out = relu(bn(x1@w1^T)) ----
            const int m0 = (job - N2_JOBS2) * 256 + wid * 16;
            const int m1 = m0 + 128;
            uint32_t Ah0[4][4], Al0[4][4], Ah1[4][4], Al1[4][4];
            load_A(x1, m0, gq, tq, Ah0, Al0);
            load_A(x1, m1, gq, tq, Ah1, Al1);
            #pragma unroll
            for (int half = 0; half < 2; half++) {
                float acc0[4][4], acc1[4][4];
                #pragma unroll
                for (int nt = 0; nt < 4; nt++)
                    #pragma unroll
                    for (int r = 0; r < 4; r++) { acc0[nt][r] = 0.f; acc1[nt][r] = 0.f; }
                run_chains_dual(acc0, acc1, packW, Ah0, Al0, Ah1, Al1, gq, tq, half * 4);
                epilogue_half(acc0, g_fbW, outp, m0, gq, tq, half * 4, true);
                epilogue_half(acc1, g_fbW, outp, m1, gq, tq, half * 4, true);
            }
        }
    }
}

// ===================== logit + exp + denom (thread per pair, float4 weights) =====================
__global__ void __launch_bounds__(256)
logit_kernel(const int* __restrict__ knn, const float* __restrict__ bs2)
{
    __shared__ float4 smem_q[64];
    const int tid = threadIdx.x;
    if (tid < 64) smem_q[tid] = g_sw34[tid];
    __syncthreads();
    const float bias2 = bs2[0];

    const int mi = blockIdx.x * 256 + tid;
    const int j  = mi >> 4;
    const int i  = knn[mi];
    float4 pq = g_p1q[i];
    float4 qq = g_p2q[j];
    float prx = pq.x - qq.x, pry = pq.y - qq.y, prz = pq.z - qq.z;

    float acc = 0.0f;
    const float4* pre4 = (const float4*)(g_pre + (size_t)j * 64);
    #pragma unroll
    for (int c4 = 0; c4 < 16; c4++) {
        float4 pv = pre4[c4];
        float4 w0 = smem_q[4*c4+0];
        float4 w1 = smem_q[4*c4+1];
        float4 w2 = smem_q[4*c4+2];
        float4 w3 = smem_q[4*c4+3];
        float h;
        h = fmaf(prx, w0.x, fmaf(pry, w0.y, fmaf(prz, w0.z, pv.x)));
        acc = fmaf(fmaxf(h, 0.f), w0.w, acc);
        h = fmaf(prx, w1.x, fmaf(pry, w1.y, fmaf(prz, w1.z, pv.y)));
        acc = fmaf(fmaxf(h, 0.f), w1.w, acc);
        h = fmaf(prx, w2.x, fmaf(pry, w2.y, fmaf(prz, w2.z, pv.z)));
        acc = fmaf(fmaxf(h, 0.f), w2.w, acc);
        h = fmaf(prx, w3.x, fmaf(pry, w3.y, fmaf(prz, w3.z, pv.w)));
        acc = fmaf(fmaxf(h, 0.f), w3.w, acc);
    }
    float ev = __expf(acc + bias2);
    g_e[mi] = ev;
    atomicAdd(&g_denom[i], ev);
}

// ========= prob-weighted scatter: 16-lane group owns one coarse point j =========
__global__ void __launch_bounds__(256)
scatter_kernel(const int* __restrict__ knn, float* __restrict__ out)
{
    const int tid  = threadIdx.x;
    const int lane = tid & 31, w = tid >> 5;
    const int half = lane >> 4;
    const int c4   = lane & 15;

    const int j  = blockIdx.x * 16 + w * 2 + half;
    const int mi = j * 16 + c4;

    const int   i_l = knn[mi];
    const float ev  = g_e[mi];
    const float dn  = g_denom[i_l];
    const float prob_l = ev * (dn > 0.f ? 1.0f / dn : 0.0f);

    const float4 u = *((const float4*)(g_upfeat + (size_t)j * 64) + c4);

    const int base = half << 4;
    #pragma unroll
    for (int k = 0; k < 16; k++) {
        float prob_b = __shfl_sync(0xffffffffu, prob_l, base + k);
        int   i_b    = __shfl_sync(0xffffffffu, i_l,    base + k);
        float4 val = make_float4(u.x * prob_b, u.y * prob_b, u.z * prob_b, u.w * prob_b);
        atomicAdd((float4*)(out + (size_t)i_b * 64) + c4, val);
    }
}

extern "C" void kernel_launch(void* const* d_in, const int* in_sizes, int n_in,
                              void* d_out, int out_size)
{
    const float* p1  = (const float*)d_in[0];
    const float* p2  = (const float*)d_in[1];
    const float* x1  = (const float*)d_in[2];
    const float* x2  = (const float*)d_in[3];
    const int*   knn = (const int*)  d_in[4];
    const float* w1  = (const float*)d_in[5];
    const float* b1  = (const float*)d_in[6];
    const float* g1  = (const float*)d_in[7];
    const float* be1 = (const float*)d_in[8];
    const float* m1  = (const float*)d_in[9];
    const float* v1  = (const float*)d_in[10];
    const float* w2  = (const float*)d_in[11];
    const float* b2  = (const float*)d_in[12];
    const float* g2  = (const float*)d_in[13];
    const float* be2 = (const float*)d_in[14];
    const float* m2  = (const float*)d_in[15];
    const float* v2  = (const float*)d_in[16];
    const float* ws1 = (const float*)d_in[17];
    const float* bs1 = (const float*)d_in[18];
    const float* gs  = (const float*)d_in[19];
    const float* bes = (const float*)d_in[20];
    const float* ms  = (const float*)d_in[21];
    const float* vs  = (const float*)d_in[22];
    const float* ws2 = (const float*)d_in[23];
    const float* bs2 = (const float*)d_in[24];
    float* out = (float*)d_out;

    // pack all weights/biases once + init denom + pack p1/p2
    prep_kernel<<<444, 256>>>(w1, b1, g1, be1, m1, v1,
                              w2, b2, g2, be2, m2, v2,
                              ws1, bs1, gs, bes, ms, vs, ws2, p1, p2);
    // ALL GEMM tiles (n2 first for balance; dual-A jobs share B loads)
    gemm_all_kernel<<<296, 256>>>(x1, x2, out);
    // logit + exp + denom
    logit_kernel<<<MPAIR/256, 256>>>(knn, bs2);
    // prob-weighted scatter on top of y1
    scatter_kernel<<<N2/16, 256>>>(knn, out);
}